// round 3
// baseline (speedup 1.0000x reference)
#include <cuda_runtime.h>
#include <math.h>
#include <stdint.h>

#define B_ 8
#define N_ 1024
#define M_ 1024
#define D_ 256
#define H_ 4
#define P_ 128
#define C_ 64

// -------- device scratch (allocation-free rule) --------
__device__ float g_q[B_ * H_ * N_ * C_];    // (B,H,N,C)
__device__ float g_k[B_ * H_ * M_ * C_];    // (B,H,M,C)
__device__ float g_v[B_ * H_ * M_ * C_];    // (B,H,M,C)

// ---------------- tf32 helpers ----------------
__device__ __forceinline__ uint32_t f2tf(float x) {
    uint32_t u;
    asm("cvt.rna.tf32.f32 %0, %1;" : "=r"(u) : "f"(x));
    return u;
}

__device__ __forceinline__ void mma8(float d[4], const uint32_t a[4], const uint32_t b[2]) {
    asm volatile(
        "mma.sync.aligned.m16n8k8.row.col.f32.tf32.tf32.f32 "
        "{%0,%1,%2,%3}, {%4,%5,%6,%7}, {%8,%9}, {%0,%1,%2,%3};"
        : "+f"(d[0]), "+f"(d[1]), "+f"(d[2]), "+f"(d[3])
        : "r"(a[0]), "r"(a[1]), "r"(a[2]), "r"(a[3]), "r"(b[0]), "r"(b[1]));
}

// ---------------- smem layout (floats) ----------------
#define S_STRIDE 1036                    // 1024 + 12 pad -> conflict-free frag loads
#define S_OFF    0                       // 32 x 1036
#define QH_OFF   33152                   // 32 x 68
#define QL_OFF   35328
#define KS_STRIDE 76                     // staged K/V/emb chunk stride
#define KH_OFF   37504                   // 64 x 76
#define KL_OFF   42368
#define SP_OFF   47232                   // 32 x 128
#define SMEM_FLOATS 51328
#define SMEM_BYTES  (SMEM_FLOATS * 4)

// ============================================================================
// Kernel 1: fused QKV projection (fp32, unchanged from R1 — known correct).
// ============================================================================
__global__ __launch_bounds__(256) void proj_kernel(
    const float* __restrict__ Xq, const float* __restrict__ Xk,
    const float* __restrict__ Xv,
    const float* __restrict__ Wq, const float* __restrict__ bq,
    const float* __restrict__ Wk, const float* __restrict__ bk,
    const float* __restrict__ Wv, const float* __restrict__ bv)
{
    const int which = blockIdx.z;
    const float* X    = (which == 0) ? Xq : (which == 1) ? Xk : Xv;
    const float* W    = (which == 0) ? Wq : (which == 1) ? Wk : Wv;
    const float* bias = (which == 0) ? bq : (which == 1) ? bk : bv;
    float* out        = (which == 0) ? g_q : (which == 1) ? g_k : g_v;

    const int r0 = blockIdx.x * 64;
    const int j0 = blockIdx.y * 64;

    __shared__ float As[16][68];
    __shared__ float Bs[16][68];

    const int tid = threadIdx.x;
    const int tx = tid & 15, ty = tid >> 4;
    const int lr  = tid >> 2;
    const int lk4 = (tid & 3) * 4;

    float acc[4][4] = {};

    for (int kc = 0; kc < 256; kc += 16) {
        float4 a = *(const float4*)&X[(size_t)(r0 + lr) * 256 + kc + lk4];
        float4 b = *(const float4*)&W[(size_t)(j0 + lr) * 256 + kc + lk4];
        As[lk4 + 0][lr] = a.x; As[lk4 + 1][lr] = a.y;
        As[lk4 + 2][lr] = a.z; As[lk4 + 3][lr] = a.w;
        Bs[lk4 + 0][lr] = b.x; Bs[lk4 + 1][lr] = b.y;
        Bs[lk4 + 2][lr] = b.z; Bs[lk4 + 3][lr] = b.w;
        __syncthreads();
#pragma unroll
        for (int kk = 0; kk < 16; kk++) {
            float av[4], bv4[4];
#pragma unroll
            for (int i = 0; i < 4; i++) av[i]  = As[kk][ty * 4 + i];
#pragma unroll
            for (int j = 0; j < 4; j++) bv4[j] = Bs[kk][tx * 4 + j];
#pragma unroll
            for (int i = 0; i < 4; i++)
#pragma unroll
                for (int j = 0; j < 4; j++)
                    acc[i][j] = fmaf(av[i], bv4[j], acc[i][j]);
        }
        __syncthreads();
    }

#pragma unroll
    for (int j = 0; j < 4; j++) {
        const int col = j0 + tx * 4 + j;
        const float bj = bias[col];
        const int h = col >> 6, c = col & 63;
#pragma unroll
        for (int i = 0; i < 4; i++) {
            const int r = r0 + ty * 4 + i;
            const int b = r >> 10, l = r & 1023;
            out[(((size_t)(b * H_ + h) * N_) + l) * C_ + c] = acc[i][j] + bj;
        }
    }
}

// ============================================================================
// Kernel 2: FUSED  sp-GEMM + scores-GEMM + gather/factor/mask + softmax
//           + attn write + AV-GEMM.  One block = 32 q-rows of one (b,h).
// tf32 mma.sync; split hi/lo precision for logits, P(single)xV(split) for AV.
// ============================================================================
__global__ __launch_bounds__(256, 1) void fused_kernel(
    const float* __restrict__ emb, const float* __restrict__ factor,
    const int* __restrict__ eidx, const unsigned char* __restrict__ kmask,
    float* __restrict__ attn, float* __restrict__ hidden)
{
    extern __shared__ float sm[];
    float*    S  = sm + S_OFF;                 // 32 x 1036 fp32 scores/probs
    uint32_t* Su = (uint32_t*)(sm + S_OFF);    // same array as tf32 bits later
    uint32_t* Qh = (uint32_t*)(sm + QH_OFF);   // 32 x 68
    uint32_t* Ql = (uint32_t*)(sm + QL_OFF);
    uint32_t* Kh = (uint32_t*)(sm + KH_OFF);   // 64 x 76 (K / V / emb chunks)
    uint32_t* Kl = (uint32_t*)(sm + KL_OFF);
    float*    Sp = sm + SP_OFF;                // 32 x 128

    const int tid  = threadIdx.x;
    const int w    = tid >> 5;      // warp 0..7
    const int lane = tid & 31;
    const int gid  = lane >> 2;     // 0..7
    const int tg   = lane & 3;      // 0..3
    const int bh = blockIdx.y, b = bh >> 2, h = bh & 3;
    const int n0 = blockIdx.x * 32;

    // ---------- stage Q (32x64) hi/lo ----------
    {
        const float* src = g_q + ((size_t)bh * N_ + n0) * C_;
#pragma unroll
        for (int j = 0; j < 2; j++) {
            int id = tid + j * 256;            // float4 id, 512 total
            int r = id >> 4, c4 = (id & 15) * 4;
            float4 v = *(const float4*)(src + (size_t)r * 64 + c4);
            float vv[4] = {v.x, v.y, v.z, v.w};
#pragma unroll
            for (int e = 0; e < 4; e++) {
                uint32_t hi = f2tf(vv[e]);
                Qh[r * 68 + c4 + e] = hi;
                Ql[r * 68 + c4 + e] = f2tf(vv[e] - __uint_as_float(hi));
            }
        }
    }

    // ---------- SP: Sp(32x128) = Q · emb_h^T  (split tf32, 2 chunks) ----------
    for (int pc = 0; pc < 2; pc++) {
        __syncthreads();
        {   // stage emb chunk: rows p = pc*64 + r, cols emb[p][h*64 + c]
            const float* src = emb + (size_t)(pc * 64) * D_ + h * 64;
#pragma unroll
            for (int j = 0; j < 4; j++) {
                int id = tid + j * 256;        // 1024 float4
                int r = id >> 4, c4 = (id & 15) * 4;
                float4 v = *(const float4*)(src + (size_t)r * D_ + c4);
                float vv[4] = {v.x, v.y, v.z, v.w};
#pragma unroll
                for (int e = 0; e < 4; e++) {
                    uint32_t hi = f2tf(vv[e]);
                    Kh[r * KS_STRIDE + c4 + e] = hi;
                    Kl[r * KS_STRIDE + c4 + e] = f2tf(vv[e] - __uint_as_float(hi));
                }
            }
        }
        __syncthreads();

        float hh[2][4] = {}, hl[2][4] = {}, lh[2][4] = {};
#pragma unroll
        for (int kb = 0; kb < 8; kb++) {
            uint32_t ah[2][4], al[2][4], bhf[2], blf[2];
#pragma unroll
            for (int mt = 0; mt < 2; mt++) {
                int r0 = mt * 16 + gid, c0 = kb * 8 + tg;
                ah[mt][0] = Qh[r0 * 68 + c0];       ah[mt][1] = Qh[(r0 + 8) * 68 + c0];
                ah[mt][2] = Qh[r0 * 68 + c0 + 4];   ah[mt][3] = Qh[(r0 + 8) * 68 + c0 + 4];
                al[mt][0] = Ql[r0 * 68 + c0];       al[mt][1] = Ql[(r0 + 8) * 68 + c0];
                al[mt][2] = Ql[r0 * 68 + c0 + 4];   al[mt][3] = Ql[(r0 + 8) * 68 + c0 + 4];
            }
            int br = w * 8 + gid, bc = kb * 8 + tg;
            bhf[0] = Kh[br * KS_STRIDE + bc]; bhf[1] = Kh[br * KS_STRIDE + bc + 4];
            blf[0] = Kl[br * KS_STRIDE + bc]; blf[1] = Kl[br * KS_STRIDE + bc + 4];
#pragma unroll
            for (int mt = 0; mt < 2; mt++) {
                mma8(hh[mt], ah[mt], bhf);
                mma8(hl[mt], ah[mt], blf);
                mma8(lh[mt], al[mt], bhf);
            }
        }
#pragma unroll
        for (int mt = 0; mt < 2; mt++) {
            int row = mt * 16 + gid;
            int col = pc * 64 + w * 8 + 2 * tg;
            float2 v0 = make_float2(hh[mt][0] + hl[mt][0] + lh[mt][0],
                                    hh[mt][1] + hl[mt][1] + lh[mt][1]);
            float2 v1 = make_float2(hh[mt][2] + hl[mt][2] + lh[mt][2],
                                    hh[mt][3] + hl[mt][3] + lh[mt][3]);
            *(float2*)(Sp + row * 128 + col)       = v0;
            *(float2*)(Sp + (row + 8) * 128 + col) = v1;
        }
    }

    // ---------- GEMM1: S(32x1024) = Q · K^T (split tf32, 16 chunks) ----------
    for (int mc = 0; mc < 16; mc++) {
        __syncthreads();
        {   // stage K chunk (64 m-rows x 64 c)
            const float* src = g_k + ((size_t)bh * M_ + mc * 64) * C_;
#pragma unroll
            for (int j = 0; j < 4; j++) {
                int id = tid + j * 256;
                int r = id >> 4, c4 = (id & 15) * 4;
                float4 v = *(const float4*)(src + (size_t)r * 64 + c4);
                float vv[4] = {v.x, v.y, v.z, v.w};
#pragma unroll
                for (int e = 0; e < 4; e++) {
                    uint32_t hi = f2tf(vv[e]);
                    Kh[r * KS_STRIDE + c4 + e] = hi;
                    Kl[r * KS_STRIDE + c4 + e] = f2tf(vv[e] - __uint_as_float(hi));
                }
            }
        }
        __syncthreads();

        float hh[2][4] = {}, hl[2][4] = {}, lh[2][4] = {};
#pragma unroll
        for (int kb = 0; kb < 8; kb++) {
            uint32_t ah[2][4], al[2][4], bhf[2], blf[2];
#pragma unroll
            for (int mt = 0; mt < 2; mt++) {
                int r0 = mt * 16 + gid, c0 = kb * 8 + tg;
                ah[mt][0] = Qh[r0 * 68 + c0];       ah[mt][1] = Qh[(r0 + 8) * 68 + c0];
                ah[mt][2] = Qh[r0 * 68 + c0 + 4];   ah[mt][3] = Qh[(r0 + 8) * 68 + c0 + 4];
                al[mt][0] = Ql[r0 * 68 + c0];       al[mt][1] = Ql[(r0 + 8) * 68 + c0];
                al[mt][2] = Ql[r0 * 68 + c0 + 4];   al[mt][3] = Ql[(r0 + 8) * 68 + c0 + 4];
            }
            int br = w * 8 + gid, bc = kb * 8 + tg;
            bhf[0] = Kh[br * KS_STRIDE + bc]; bhf[1] = Kh[br * KS_STRIDE + bc + 4];
            blf[0] = Kl[br * KS_STRIDE + bc]; blf[1] = Kl[br * KS_STRIDE + bc + 4];
#pragma unroll
            for (int mt = 0; mt < 2; mt++) {
                mma8(hh[mt], ah[mt], bhf);
                mma8(hl[mt], ah[mt], blf);
                mma8(lh[mt], al[mt], bhf);
            }
        }
#pragma unroll
        for (int mt = 0; mt < 2; mt++) {
            int row = mt * 16 + gid;
            int col = mc * 64 + w * 8 + 2 * tg;
            float2 v0 = make_float2(hh[mt][0] + hl[mt][0] + lh[mt][0],
                                    hh[mt][1] + hl[mt][1] + lh[mt][1]);
            float2 v1 = make_float2(hh[mt][2] + hl[mt][2] + lh[mt][2],
                                    hh[mt][3] + hl[mt][3] + lh[mt][3]);
            *(float2*)(S + row * S_STRIDE + col)       = v0;
            *(float2*)(S + (row + 8) * S_STRIDE + col) = v1;
        }
    }
    __syncthreads();

    // ---------- epilogue: gather sp, factor, scale, mask ----------
#pragma unroll 4
    for (int it = 0; it < 32; it++) {
        const int row = it;
        const int c4  = tid * 4;
        const size_t gbase = ((size_t)(b * N_ + n0 + row)) * M_ + c4;
        float4 sc = *(float4*)(S + row * S_STRIDE + c4);
        int4   id = *(const int4*)(eidx + gbase);
        float4 fa = *(const float4*)(factor + gbase);
        const float* sprow = Sp + row * 128;
        float r0 = fa.x * (sc.x + sprow[id.x]) * 0.125f;
        float r1 = fa.y * (sc.y + sprow[id.y]) * 0.125f;
        float r2 = fa.z * (sc.z + sprow[id.z]) * 0.125f;
        float r3 = fa.w * (sc.w + sprow[id.w]) * 0.125f;
        const unsigned char* km = kmask + b * M_ + c4;
        if (km[0]) r0 = -INFINITY;
        if (km[1]) r1 = -INFINITY;
        if (km[2]) r2 = -INFINITY;
        if (km[3]) r3 = -INFINITY;
        *(float4*)(S + row * S_STRIDE + c4) = make_float4(r0, r1, r2, r3);
    }
    __syncthreads();

    // ---------- softmax (warp w owns rows w*4 .. w*4+3) ----------
    for (int rr = 0; rr < 4; rr++) {
        const int row = w * 4 + rr;
        float vals[32];
        float mx = -INFINITY;
#pragma unroll
        for (int j = 0; j < 8; j++) {
            float4 v = *(float4*)(S + row * S_STRIDE + (j * 32 + lane) * 4);
            vals[j * 4 + 0] = v.x; vals[j * 4 + 1] = v.y;
            vals[j * 4 + 2] = v.z; vals[j * 4 + 3] = v.w;
            mx = fmaxf(mx, fmaxf(fmaxf(v.x, v.y), fmaxf(v.z, v.w)));
        }
#pragma unroll
        for (int off = 16; off > 0; off >>= 1)
            mx = fmaxf(mx, __shfl_xor_sync(0xffffffffu, mx, off));
        float sum = 0.f;
#pragma unroll
        for (int i = 0; i < 32; i++) { vals[i] = __expf(vals[i] - mx); sum += vals[i]; }
#pragma unroll
        for (int off = 16; off > 0; off >>= 1)
            sum += __shfl_xor_sync(0xffffffffu, sum, off);
        const float inv = 1.0f / sum;
        const size_t abase = ((size_t)(bh * N_ + n0 + row)) * M_;
#pragma unroll
        for (int j = 0; j < 8; j++) {
            const int c4 = (j * 32 + lane) * 4;
            float p0 = vals[j * 4 + 0] * inv, p1 = vals[j * 4 + 1] * inv;
            float p2 = vals[j * 4 + 2] * inv, p3 = vals[j * 4 + 3] * inv;
            *(float4*)(attn + abase + c4) = make_float4(p0, p1, p2, p3);
            uint4 t = make_uint4(f2tf(p0), f2tf(p1), f2tf(p2), f2tf(p3));
            *(uint4*)(Su + row * S_STRIDE + c4) = t;  // tf32 bits for AV
        }
    }

    // ---------- AV: hidden(32x64) = P · V (P single tf32, V split) ----------
    float avh[2][4] = {}, avl[2][4] = {};
    for (int kc = 0; kc < 16; kc++) {
        __syncthreads();   // protect Kh/Kl reuse
        {   // stage V chunk (64 k-rows x 64 c)
            const float* src = g_v + ((size_t)bh * M_ + kc * 64) * C_;
#pragma unroll
            for (int j = 0; j < 4; j++) {
                int id = tid + j * 256;
                int r = id >> 4, c4 = (id & 15) * 4;
                float4 v = *(const float4*)(src + (size_t)r * 64 + c4);
                float vv[4] = {v.x, v.y, v.z, v.w};
#pragma unroll
                for (int e = 0; e < 4; e++) {
                    uint32_t hi = f2tf(vv[e]);
                    Kh[r * KS_STRIDE + c4 + e] = hi;
                    Kl[r * KS_STRIDE + c4 + e] = f2tf(vv[e] - __uint_as_float(hi));
                }
            }
        }
        __syncthreads();

#pragma unroll
        for (int kb = 0; kb < 8; kb++) {
            uint32_t a[2][4];
            const int cbase = kc * 64 + kb * 8;
#pragma unroll
            for (int mt = 0; mt < 2; mt++) {
                int r0 = mt * 16 + gid;
                a[mt][0] = Su[r0 * S_STRIDE + cbase + tg];
                a[mt][1] = Su[(r0 + 8) * S_STRIDE + cbase + tg];
                a[mt][2] = Su[r0 * S_STRIDE + cbase + tg + 4];
                a[mt][3] = Su[(r0 + 8) * S_STRIDE + cbase + tg + 4];
            }
            uint32_t bhf[2], blf[2];
            bhf[0] = Kh[(kb * 8 + tg) * KS_STRIDE + w * 8 + gid];
            bhf[1] = Kh[(kb * 8 + tg + 4) * KS_STRIDE + w * 8 + gid];
            blf[0] = Kl[(kb * 8 + tg) * KS_STRIDE + w * 8 + gid];
            blf[1] = Kl[(kb * 8 + tg + 4) * KS_STRIDE + w * 8 + gid];
#pragma unroll
            for (int mt = 0; mt < 2; mt++) {
                mma8(avh[mt], a[mt], bhf);
                mma8(avl[mt], a[mt], blf);
            }
        }
    }

    // store hidden: rows n0 + mt*16 + gid(+8), cols h*64 + w*8 + 2tg(+1)
#pragma unroll
    for (int mt = 0; mt < 2; mt++) {
        const int row = n0 + mt * 16 + gid;
        const int col = h * 64 + w * 8 + 2 * tg;
        float2 v0 = make_float2(avh[mt][0] + avl[mt][0], avh[mt][1] + avl[mt][1]);
        float2 v1 = make_float2(avh[mt][2] + avl[mt][2], avh[mt][3] + avl[mt][3]);
        *(float2*)(hidden + ((size_t)b * N_ + row) * D_ + col)       = v0;
        *(float2*)(hidden + ((size_t)b * N_ + row + 8) * D_ + col)   = v1;
    }
}

// ============================================================================
// Launch
// ============================================================================
extern "C" void kernel_launch(void* const* d_in, const int* in_sizes, int n_in,
                              void* d_out, int out_size)
{
    const float* input_q = (const float*)d_in[0];
    const float* input_k = (const float*)d_in[1];
    const float* input_v = (const float*)d_in[2];
    const float* Wq = (const float*)d_in[3];
    const float* bq = (const float*)d_in[4];
    const float* Wk = (const float*)d_in[5];
    const float* bk = (const float*)d_in[6];
    const float* Wv = (const float*)d_in[7];
    const float* bv = (const float*)d_in[8];
    const float* emb_table = (const float*)d_in[9];
    const float* factor = (const float*)d_in[10];
    const int* eidx = (const int*)d_in[11];
    const unsigned char* kmask = (const unsigned char*)d_in[12];

    float* hidden = (float*)d_out;                          // (B,N,D)
    float* attn   = (float*)d_out + (size_t)B_ * N_ * D_;   // (B,H,N,M)

    static int smem_set = 0;
    if (!smem_set) {
        cudaFuncSetAttribute(fused_kernel,
                             cudaFuncAttributeMaxDynamicSharedMemorySize, SMEM_BYTES);
        smem_set = 1;
    }

    proj_kernel<<<dim3((B_ * N_) / 64, D_ / 64, 3), 256>>>(
        input_q, input_k, input_v, Wq, bq, Wk, bk, Wv, bv);

    fused_kernel<<<dim3(N_ / 32, B_ * H_), 256, SMEM_BYTES>>>(
        emb_table, factor, eidx, kmask, attn, hidden);
}

// round 4
// speedup vs baseline: 1.0258x; 1.0258x over previous
#include <cuda_runtime.h>
#include <math.h>
#include <stdint.h>

#define B_ 8
#define N_ 1024
#define M_ 1024
#define D_ 256
#define H_ 4
#define P_ 128
#define C_ 64

// -------- device scratch: pre-split tf32 hi/lo operands --------
__device__ uint32_t g_qh[B_ * H_ * N_ * C_];
__device__ uint32_t g_ql[B_ * H_ * N_ * C_];
__device__ uint32_t g_kh[B_ * H_ * M_ * C_];
__device__ uint32_t g_kl[B_ * H_ * M_ * C_];
__device__ uint32_t g_vh[B_ * H_ * M_ * C_];
__device__ uint32_t g_vl[B_ * H_ * M_ * C_];
__device__ uint32_t g_eh[P_ * D_];
__device__ uint32_t g_el[P_ * D_];

// ---------------- tf32 helpers ----------------
__device__ __forceinline__ uint32_t f2tf(float x) {
    uint32_t u;
    asm("cvt.rna.tf32.f32 %0, %1;" : "=r"(u) : "f"(x));
    return u;
}

__device__ __forceinline__ void mma8(float d[4], const uint32_t a[4], const uint32_t b[2]) {
    asm volatile(
        "mma.sync.aligned.m16n8k8.row.col.f32.tf32.tf32.f32 "
        "{%0,%1,%2,%3}, {%4,%5,%6,%7}, {%8,%9}, {%0,%1,%2,%3};"
        : "+f"(d[0]), "+f"(d[1]), "+f"(d[2]), "+f"(d[3])
        : "r"(a[0]), "r"(a[1]), "r"(a[2]), "r"(a[3]), "r"(b[0]), "r"(b[1]));
}

// ---------------- smem layout (float units) ----------------
#define S_STRIDE 1036
#define QH_OFF   33152
#define QL_OFF   35328
#define KS_STRIDE 76
#define KH_OFF   37504
#define KL_OFF   42368
#define SP_OFF   47232
#define SMEM_FLOATS 51328
#define SMEM_BYTES  (SMEM_FLOATS * 4)

// ============================================================================
// Kernel 1: fused QKV projection (fp32 math), epilogue writes tf32 hi/lo.
// ============================================================================
__global__ __launch_bounds__(256) void proj_kernel(
    const float* __restrict__ Xq, const float* __restrict__ Xk,
    const float* __restrict__ Xv,
    const float* __restrict__ Wq, const float* __restrict__ bq,
    const float* __restrict__ Wk, const float* __restrict__ bk,
    const float* __restrict__ Wv, const float* __restrict__ bv)
{
    const int which = blockIdx.z;
    const float* X    = (which == 0) ? Xq : (which == 1) ? Xk : Xv;
    const float* W    = (which == 0) ? Wq : (which == 1) ? Wk : Wv;
    const float* bias = (which == 0) ? bq : (which == 1) ? bk : bv;
    uint32_t* outh    = (which == 0) ? g_qh : (which == 1) ? g_kh : g_vh;
    uint32_t* outl    = (which == 0) ? g_ql : (which == 1) ? g_kl : g_vl;

    const int r0 = blockIdx.x * 64;
    const int j0 = blockIdx.y * 64;

    __shared__ float As[16][68];
    __shared__ float Bs[16][68];

    const int tid = threadIdx.x;
    const int tx = tid & 15, ty = tid >> 4;
    const int lr  = tid >> 2;
    const int lk4 = (tid & 3) * 4;

    float acc[4][4] = {};

    for (int kc = 0; kc < 256; kc += 16) {
        float4 a = *(const float4*)&X[(size_t)(r0 + lr) * 256 + kc + lk4];
        float4 b = *(const float4*)&W[(size_t)(j0 + lr) * 256 + kc + lk4];
        As[lk4 + 0][lr] = a.x; As[lk4 + 1][lr] = a.y;
        As[lk4 + 2][lr] = a.z; As[lk4 + 3][lr] = a.w;
        Bs[lk4 + 0][lr] = b.x; Bs[lk4 + 1][lr] = b.y;
        Bs[lk4 + 2][lr] = b.z; Bs[lk4 + 3][lr] = b.w;
        __syncthreads();
#pragma unroll
        for (int kk = 0; kk < 16; kk++) {
            float av[4], bv4[4];
#pragma unroll
            for (int i = 0; i < 4; i++) av[i]  = As[kk][ty * 4 + i];
#pragma unroll
            for (int j = 0; j < 4; j++) bv4[j] = Bs[kk][tx * 4 + j];
#pragma unroll
            for (int i = 0; i < 4; i++)
#pragma unroll
                for (int j = 0; j < 4; j++)
                    acc[i][j] = fmaf(av[i], bv4[j], acc[i][j]);
        }
        __syncthreads();
    }

#pragma unroll
    for (int j = 0; j < 4; j++) {
        const int col = j0 + tx * 4 + j;
        const float bj = bias[col];
        const int h = col >> 6, c = col & 63;
#pragma unroll
        for (int i = 0; i < 4; i++) {
            const int r = r0 + ty * 4 + i;
            const int b = r >> 10, l = r & 1023;
            const size_t idx = (((size_t)(b * H_ + h) * N_) + l) * C_ + c;
            const float v = acc[i][j] + bj;
            const uint32_t hi = f2tf(v);
            outh[idx] = hi;
            outl[idx] = f2tf(v - __uint_as_float(hi));
        }
    }
}

// ============================================================================
// Kernel 1b: split emb table into tf32 hi/lo.
// ============================================================================
__global__ __launch_bounds__(256) void emb_split_kernel(const float* __restrict__ emb)
{
    const int i = blockIdx.x * 256 + threadIdx.x;
    const float v = emb[i];
    const uint32_t hi = f2tf(v);
    g_eh[i] = hi;
    g_el[i] = f2tf(v - __uint_as_float(hi));
}

// ============================================================================
// Kernel 2: FUSED  sp + scores + gather/factor/mask + softmax + attn + AV.
// 512 threads (16 warps): warp w -> mt = w>>3 (row half), wm = w&7 (col group).
// Register-pipelined chunk staging; operands pre-split in gmem (no cvt here).
// ============================================================================
__global__ __launch_bounds__(512, 1) void fused_kernel(
    const float* __restrict__ factor, const int* __restrict__ eidx,
    const unsigned char* __restrict__ kmask,
    float* __restrict__ attn, float* __restrict__ hidden)
{
    extern __shared__ float smf[];
    float*    S  = smf;
    uint32_t* Su = (uint32_t*)smf;
    uint32_t* Qh = (uint32_t*)(smf + QH_OFF);
    uint32_t* Ql = (uint32_t*)(smf + QL_OFF);
    uint32_t* Kh = (uint32_t*)(smf + KH_OFF);
    uint32_t* Kl = (uint32_t*)(smf + KL_OFF);
    float*    Sp = smf + SP_OFF;

    const int tid  = threadIdx.x;
    const int w    = tid >> 5;
    const int lane = tid & 31;
    const int gid  = lane >> 2;
    const int tg   = lane & 3;
    const int wm   = w & 7;        // column group within 64-wide chunk
    const int mt   = w >> 3;       // row half (0: rows 0-15, 1: rows 16-31)
    const int bh = blockIdx.y, b = bh >> 2, h = bh & 3;
    const int n0 = blockIdx.x * 32;
    const int r0 = mt * 16 + gid;

    // ---------- stage Q (32x64 hi/lo): one uint4 per thread per array ----------
    {
        const uint32_t* qh = g_qh + ((size_t)bh * N_ + n0) * C_;
        const uint32_t* ql = g_ql + ((size_t)bh * N_ + n0) * C_;
        const int r = tid >> 4, c4 = (tid & 15) * 4;
        *(uint4*)&Qh[r * 68 + c4] = *(const uint4*)&qh[r * 64 + c4];
        *(uint4*)&Ql[r * 68 + c4] = *(const uint4*)&ql[r * 64 + c4];
    }
    __syncthreads();

    // ---------- preload Q-hi fragments (reused by SP and GEMM1) ----------
    uint32_t qfh[8][4];
#pragma unroll
    for (int kb = 0; kb < 8; kb++) {
        const int c0 = kb * 8 + tg;
        qfh[kb][0] = Qh[r0 * 68 + c0];
        qfh[kb][1] = Qh[(r0 + 8) * 68 + c0];
        qfh[kb][2] = Qh[r0 * 68 + c0 + 4];
        qfh[kb][3] = Qh[(r0 + 8) * 68 + c0 + 4];
    }

    const uint32_t* kh_base = g_kh + (size_t)bh * M_ * C_;
    const uint32_t* kl_base = g_kl + (size_t)bh * M_ * C_;
    const uint32_t* vh_base = g_vh + (size_t)bh * M_ * C_;
    const uint32_t* vl_base = g_vl + (size_t)bh * M_ * C_;

    // prefetch K chunk 0 into registers (overlaps SP phase)
    uint4 sh0, sh1, sl0, sl1;
    sh0 = *(const uint4*)&kh_base[(size_t)tid * 4];
    sh1 = *(const uint4*)&kh_base[(size_t)(tid + 512) * 4];
    sl0 = *(const uint4*)&kl_base[(size_t)tid * 4];
    sl1 = *(const uint4*)&kl_base[(size_t)(tid + 512) * 4];

    // ---------- SP: Sp(32x128) = Q · emb_h^T ----------
    for (int pc = 0; pc < 2; pc++) {
        __syncthreads();
        {
            const uint32_t* eh = g_eh + (size_t)(pc * 64) * D_ + h * 64;
            const uint32_t* el = g_el + (size_t)(pc * 64) * D_ + h * 64;
#pragma unroll
            for (int j = 0; j < 2; j++) {
                const int id = tid + j * 512;
                const int r = id >> 4, c4 = (id & 15) * 4;
                *(uint4*)&Kh[r * KS_STRIDE + c4] = *(const uint4*)&eh[(size_t)r * D_ + c4];
                *(uint4*)&Kl[r * KS_STRIDE + c4] = *(const uint4*)&el[(size_t)r * D_ + c4];
            }
        }
        __syncthreads();

        float hh[4] = {}, hl[4] = {}, lh[4] = {};
#pragma unroll
        for (int kb = 0; kb < 8; kb++) {
            const int c0 = kb * 8 + tg;
            uint32_t al[4];
            al[0] = Ql[r0 * 68 + c0];       al[1] = Ql[(r0 + 8) * 68 + c0];
            al[2] = Ql[r0 * 68 + c0 + 4];   al[3] = Ql[(r0 + 8) * 68 + c0 + 4];
            const int br = wm * 8 + gid, bc = kb * 8 + tg;
            uint32_t bhf[2] = {Kh[br * KS_STRIDE + bc], Kh[br * KS_STRIDE + bc + 4]};
            uint32_t blf[2] = {Kl[br * KS_STRIDE + bc], Kl[br * KS_STRIDE + bc + 4]};
            mma8(hh, qfh[kb], bhf);
            mma8(hl, qfh[kb], blf);
            mma8(lh, al, bhf);
        }
        const int col = pc * 64 + wm * 8 + 2 * tg;
        *(float2*)(Sp + r0 * 128 + col) =
            make_float2(hh[0] + hl[0] + lh[0], hh[1] + hl[1] + lh[1]);
        *(float2*)(Sp + (r0 + 8) * 128 + col) =
            make_float2(hh[2] + hl[2] + lh[2], hh[3] + hl[3] + lh[3]);
    }

    // ---------- GEMM1: S(32x1024) = Q · K^T, register-pipelined ----------
    for (int mc = 0; mc < 16; mc++) {
        __syncthreads();
        {   // commit prefetched chunk to smem
            int r = tid >> 4, c4 = (tid & 15) * 4;
            *(uint4*)&Kh[r * KS_STRIDE + c4] = sh0;
            *(uint4*)&Kl[r * KS_STRIDE + c4] = sl0;
            const int id = tid + 512;
            r = id >> 4; c4 = (id & 15) * 4;
            *(uint4*)&Kh[r * KS_STRIDE + c4] = sh1;
            *(uint4*)&Kl[r * KS_STRIDE + c4] = sl1;
        }
        if (mc < 15) {  // prefetch next chunk (overlaps MMA below)
            const size_t off = (size_t)(mc + 1) * 4096;
            sh0 = *(const uint4*)&kh_base[off + (size_t)tid * 4];
            sh1 = *(const uint4*)&kh_base[off + (size_t)(tid + 512) * 4];
            sl0 = *(const uint4*)&kl_base[off + (size_t)tid * 4];
            sl1 = *(const uint4*)&kl_base[off + (size_t)(tid + 512) * 4];
        }
        __syncthreads();

        float hh[4] = {}, hl[4] = {}, lh[4] = {};
#pragma unroll
        for (int kb = 0; kb < 8; kb++) {
            const int c0 = kb * 8 + tg;
            uint32_t al[4];
            al[0] = Ql[r0 * 68 + c0];       al[1] = Ql[(r0 + 8) * 68 + c0];
            al[2] = Ql[r0 * 68 + c0 + 4];   al[3] = Ql[(r0 + 8) * 68 + c0 + 4];
            const int br = wm * 8 + gid, bc = kb * 8 + tg;
            uint32_t bhf[2] = {Kh[br * KS_STRIDE + bc], Kh[br * KS_STRIDE + bc + 4]};
            uint32_t blf[2] = {Kl[br * KS_STRIDE + bc], Kl[br * KS_STRIDE + bc + 4]};
            mma8(hh, qfh[kb], bhf);
            mma8(hl, qfh[kb], blf);
            mma8(lh, al, bhf);
        }
        const int col = mc * 64 + wm * 8 + 2 * tg;
        *(float2*)(S + r0 * S_STRIDE + col) =
            make_float2(hh[0] + hl[0] + lh[0], hh[1] + hl[1] + lh[1]);
        *(float2*)(S + (r0 + 8) * S_STRIDE + col) =
            make_float2(hh[2] + hl[2] + lh[2], hh[3] + hl[3] + lh[3]);
    }
    __syncthreads();

    // prefetch V chunk 0 (overlaps epilogue + softmax)
    sh0 = *(const uint4*)&vh_base[(size_t)tid * 4];
    sh1 = *(const uint4*)&vh_base[(size_t)(tid + 512) * 4];
    sl0 = *(const uint4*)&vl_base[(size_t)tid * 4];
    sl1 = *(const uint4*)&vl_base[(size_t)(tid + 512) * 4];

    // ---------- epilogue: gather sp, factor, scale, mask ----------
    {
        const int half = tid >> 8, t2 = tid & 255;
        const int c4 = t2 * 4;
#pragma unroll 4
        for (int it = 0; it < 16; it++) {
            const int row = it * 2 + half;
            const size_t gbase = ((size_t)(b * N_ + n0 + row)) * M_ + c4;
            float4 sc = *(float4*)(S + row * S_STRIDE + c4);
            int4   id = *(const int4*)(eidx + gbase);
            float4 fa = *(const float4*)(factor + gbase);
            const float* sprow = Sp + row * 128;
            float e0 = fa.x * (sc.x + sprow[id.x]) * 0.125f;
            float e1 = fa.y * (sc.y + sprow[id.y]) * 0.125f;
            float e2 = fa.z * (sc.z + sprow[id.z]) * 0.125f;
            float e3 = fa.w * (sc.w + sprow[id.w]) * 0.125f;
            const unsigned char* km = kmask + b * M_ + c4;
            if (km[0]) e0 = -INFINITY;
            if (km[1]) e1 = -INFINITY;
            if (km[2]) e2 = -INFINITY;
            if (km[3]) e3 = -INFINITY;
            *(float4*)(S + row * S_STRIDE + c4) = make_float4(e0, e1, e2, e3);
        }
    }
    __syncthreads();

    // ---------- softmax: warp w owns rows 2w, 2w+1 ----------
    for (int rr = 0; rr < 2; rr++) {
        const int row = w * 2 + rr;
        float vals[32];
        float mx = -INFINITY;
#pragma unroll
        for (int j = 0; j < 8; j++) {
            float4 v = *(float4*)(S + row * S_STRIDE + (j * 32 + lane) * 4);
            vals[j * 4 + 0] = v.x; vals[j * 4 + 1] = v.y;
            vals[j * 4 + 2] = v.z; vals[j * 4 + 3] = v.w;
            mx = fmaxf(mx, fmaxf(fmaxf(v.x, v.y), fmaxf(v.z, v.w)));
        }
#pragma unroll
        for (int off = 16; off > 0; off >>= 1)
            mx = fmaxf(mx, __shfl_xor_sync(0xffffffffu, mx, off));
        float sum = 0.f;
#pragma unroll
        for (int i = 0; i < 32; i++) { vals[i] = __expf(vals[i] - mx); sum += vals[i]; }
#pragma unroll
        for (int off = 16; off > 0; off >>= 1)
            sum += __shfl_xor_sync(0xffffffffu, sum, off);
        const float inv = 1.0f / sum;
        const size_t abase = ((size_t)(bh * N_ + n0 + row)) * M_;
#pragma unroll
        for (int j = 0; j < 8; j++) {
            const int c4 = (j * 32 + lane) * 4;
            const float p0 = vals[j * 4 + 0] * inv, p1 = vals[j * 4 + 1] * inv;
            const float p2 = vals[j * 4 + 2] * inv, p3 = vals[j * 4 + 3] * inv;
            *(float4*)(attn + abase + c4) = make_float4(p0, p1, p2, p3);
            uint4 t = make_uint4(f2tf(p0), f2tf(p1), f2tf(p2), f2tf(p3));
            *(uint4*)(Su + row * S_STRIDE + c4) = t;
        }
    }

    // ---------- AV: hidden(32x64) = P · V, register-pipelined ----------
    float avh[4] = {}, avl[4] = {};
    for (int kc = 0; kc < 16; kc++) {
        __syncthreads();
        {
            int r = tid >> 4, c4 = (tid & 15) * 4;
            *(uint4*)&Kh[r * KS_STRIDE + c4] = sh0;
            *(uint4*)&Kl[r * KS_STRIDE + c4] = sl0;
            const int id = tid + 512;
            r = id >> 4; c4 = (id & 15) * 4;
            *(uint4*)&Kh[r * KS_STRIDE + c4] = sh1;
            *(uint4*)&Kl[r * KS_STRIDE + c4] = sl1;
        }
        if (kc < 15) {
            const size_t off = (size_t)(kc + 1) * 4096;
            sh0 = *(const uint4*)&vh_base[off + (size_t)tid * 4];
            sh1 = *(const uint4*)&vh_base[off + (size_t)(tid + 512) * 4];
            sl0 = *(const uint4*)&vl_base[off + (size_t)tid * 4];
            sl1 = *(const uint4*)&vl_base[off + (size_t)(tid + 512) * 4];
        }
        __syncthreads();

#pragma unroll
        for (int kb = 0; kb < 8; kb++) {
            const int cbase = kc * 64 + kb * 8;
            uint32_t a[4];
            a[0] = Su[r0 * S_STRIDE + cbase + tg];
            a[1] = Su[(r0 + 8) * S_STRIDE + cbase + tg];
            a[2] = Su[r0 * S_STRIDE + cbase + tg + 4];
            a[3] = Su[(r0 + 8) * S_STRIDE + cbase + tg + 4];
            uint32_t bhf[2], blf[2];
            bhf[0] = Kh[(kb * 8 + tg) * KS_STRIDE + wm * 8 + gid];
            bhf[1] = Kh[(kb * 8 + tg + 4) * KS_STRIDE + wm * 8 + gid];
            blf[0] = Kl[(kb * 8 + tg) * KS_STRIDE + wm * 8 + gid];
            blf[1] = Kl[(kb * 8 + tg + 4) * KS_STRIDE + wm * 8 + gid];
            mma8(avh, a, bhf);
            mma8(avl, a, blf);
        }
    }

    // store hidden
    {
        const int row = n0 + r0;
        const int col = h * 64 + wm * 8 + 2 * tg;
        *(float2*)(hidden + ((size_t)b * N_ + row) * D_ + col) =
            make_float2(avh[0] + avl[0], avh[1] + avl[1]);
        *(float2*)(hidden + ((size_t)b * N_ + row + 8) * D_ + col) =
            make_float2(avh[2] + avl[2], avh[3] + avl[3]);
    }
}

// ============================================================================
// Launch
// ============================================================================
extern "C" void kernel_launch(void* const* d_in, const int* in_sizes, int n_in,
                              void* d_out, int out_size)
{
    const float* input_q = (const float*)d_in[0];
    const float* input_k = (const float*)d_in[1];
    const float* input_v = (const float*)d_in[2];
    const float* Wq = (const float*)d_in[3];
    const float* bq = (const float*)d_in[4];
    const float* Wk = (const float*)d_in[5];
    const float* bk = (const float*)d_in[6];
    const float* Wv = (const float*)d_in[7];
    const float* bv = (const float*)d_in[8];
    const float* emb_table = (const float*)d_in[9];
    const float* factor = (const float*)d_in[10];
    const int* eidx = (const int*)d_in[11];
    const unsigned char* kmask = (const unsigned char*)d_in[12];

    float* hidden = (float*)d_out;                          // (B,N,D)
    float* attn   = (float*)d_out + (size_t)B_ * N_ * D_;   // (B,H,N,M)

    static int smem_set = 0;
    if (!smem_set) {
        cudaFuncSetAttribute(fused_kernel,
                             cudaFuncAttributeMaxDynamicSharedMemorySize, SMEM_BYTES);
        smem_set = 1;
    }

    proj_kernel<<<dim3((B_ * N_) / 64, D_ / 64, 3), 256>>>(
        input_q, input_k, input_v, Wq, bq, Wk, bk, Wv, bv);

    emb_split_kernel<<<(P_ * D_) / 256, 256>>>(emb_table);

    fused_kernel<<<dim3(N_ / 32, B_ * H_), 512, SMEM_BYTES>>>(
        factor, eidx, kmask, attn, hidden);
}

// round 5
// speedup vs baseline: 1.1482x; 1.1193x over previous
#include <cuda_runtime.h>
#include <math.h>
#include <stdint.h>

#define B_ 8
#define N_ 1024
#define M_ 1024
#define D_ 256
#define H_ 4
#define P_ 128
#define C_ 64

// -------- device scratch: pre-split tf32 hi/lo operands --------
__device__ uint32_t g_qh[B_ * H_ * N_ * C_];
__device__ uint32_t g_ql[B_ * H_ * N_ * C_];
__device__ uint32_t g_kh[B_ * H_ * M_ * C_];
__device__ uint32_t g_kl[B_ * H_ * M_ * C_];
__device__ uint32_t g_vh[B_ * H_ * M_ * C_];
__device__ uint32_t g_vl[B_ * H_ * M_ * C_];
__device__ uint32_t g_eh[P_ * D_];
__device__ uint32_t g_el[P_ * D_];

// ---------------- tf32 helpers ----------------
__device__ __forceinline__ uint32_t f2tf(float x) {
    uint32_t u;
    asm("cvt.rna.tf32.f32 %0, %1;" : "=r"(u) : "f"(x));
    return u;
}

__device__ __forceinline__ void mma8(float d[4], const uint32_t a[4], const uint32_t b[2]) {
    asm volatile(
        "mma.sync.aligned.m16n8k8.row.col.f32.tf32.tf32.f32 "
        "{%0,%1,%2,%3}, {%4,%5,%6,%7}, {%8,%9}, {%0,%1,%2,%3};"
        : "+f"(d[0]), "+f"(d[1]), "+f"(d[2]), "+f"(d[3])
        : "r"(a[0]), "r"(a[1]), "r"(a[2]), "r"(a[3]), "r"(b[0]), "r"(b[1]));
}

// ---------------- smem layout (float units) ----------------
#define S_STRIDE  1036                 // conflict-free fragment loads
#define KS_STRIDE 76
#define KH0_OFF   33152                // 64 x 76 each
#define KL0_OFF   38016
#define KH1_OFF   42880
#define KL1_OFF   47744
#define SP_STRIDE 132
#define SP_OFF    52608                // 32 x 132
#define SMEM_FLOATS 56832
#define SMEM_BYTES  (SMEM_FLOATS * 4)  // 227328 B

// ============================================================================
// Kernel 1: fused QKV projection (fp32), epilogue writes tf32 hi/lo.
// ============================================================================
__global__ __launch_bounds__(256) void proj_kernel(
    const float* __restrict__ Xq, const float* __restrict__ Xk,
    const float* __restrict__ Xv,
    const float* __restrict__ Wq, const float* __restrict__ bq,
    const float* __restrict__ Wk, const float* __restrict__ bk,
    const float* __restrict__ Wv, const float* __restrict__ bv)
{
    const int which = blockIdx.z;
    const float* X    = (which == 0) ? Xq : (which == 1) ? Xk : Xv;
    const float* W    = (which == 0) ? Wq : (which == 1) ? Wk : Wv;
    const float* bias = (which == 0) ? bq : (which == 1) ? bk : bv;
    uint32_t* outh    = (which == 0) ? g_qh : (which == 1) ? g_kh : g_vh;
    uint32_t* outl    = (which == 0) ? g_ql : (which == 1) ? g_kl : g_vl;

    const int r0 = blockIdx.x * 64;
    const int j0 = blockIdx.y * 64;

    __shared__ float As[16][68];
    __shared__ float Bs[16][68];

    const int tid = threadIdx.x;
    const int tx = tid & 15, ty = tid >> 4;
    const int lr  = tid >> 2;
    const int lk4 = (tid & 3) * 4;

    float acc[4][4] = {};

    for (int kc = 0; kc < 256; kc += 16) {
        float4 a = *(const float4*)&X[(size_t)(r0 + lr) * 256 + kc + lk4];
        float4 b = *(const float4*)&W[(size_t)(j0 + lr) * 256 + kc + lk4];
        As[lk4 + 0][lr] = a.x; As[lk4 + 1][lr] = a.y;
        As[lk4 + 2][lr] = a.z; As[lk4 + 3][lr] = a.w;
        Bs[lk4 + 0][lr] = b.x; Bs[lk4 + 1][lr] = b.y;
        Bs[lk4 + 2][lr] = b.z; Bs[lk4 + 3][lr] = b.w;
        __syncthreads();
#pragma unroll
        for (int kk = 0; kk < 16; kk++) {
            float av[4], bv4[4];
#pragma unroll
            for (int i = 0; i < 4; i++) av[i]  = As[kk][ty * 4 + i];
#pragma unroll
            for (int j = 0; j < 4; j++) bv4[j] = Bs[kk][tx * 4 + j];
#pragma unroll
            for (int i = 0; i < 4; i++)
#pragma unroll
                for (int j = 0; j < 4; j++)
                    acc[i][j] = fmaf(av[i], bv4[j], acc[i][j]);
        }
        __syncthreads();
    }

#pragma unroll
    for (int j = 0; j < 4; j++) {
        const int col = j0 + tx * 4 + j;
        const float bj = bias[col];
        const int h = col >> 6, c = col & 63;
#pragma unroll
        for (int i = 0; i < 4; i++) {
            const int r = r0 + ty * 4 + i;
            const int b = r >> 10, l = r & 1023;
            const size_t idx = (((size_t)(b * H_ + h) * N_) + l) * C_ + c;
            const float v = acc[i][j] + bj;
            const uint32_t hi = f2tf(v);
            outh[idx] = hi;
            outl[idx] = f2tf(v - __uint_as_float(hi));
        }
    }
}

// ============================================================================
// Kernel 1b: split emb table into tf32 hi/lo.
// ============================================================================
__global__ __launch_bounds__(256) void emb_split_kernel(const float* __restrict__ emb)
{
    const int i = blockIdx.x * 256 + threadIdx.x;
    const float v = emb[i];
    const uint32_t hi = f2tf(v);
    g_eh[i] = hi;
    g_el[i] = f2tf(v - __uint_as_float(hi));
}

// ============================================================================
// Kernel 2: FUSED sp + scores + gather/factor/mask + softmax + attn + AV.
// 512 threads. Q hi/lo fragments in registers; double-buffered chunk staging
// with ONE barrier per chunk (STS overlaps previous chunk's MMA).
// ============================================================================
__global__ __launch_bounds__(512, 1) void fused_kernel(
    const float* __restrict__ factor, const int* __restrict__ eidx,
    const unsigned char* __restrict__ kmask,
    float* __restrict__ attn, float* __restrict__ hidden)
{
    extern __shared__ float smf[];
    float*    S   = smf;
    uint32_t* Su  = (uint32_t*)smf;
    uint32_t* KH0 = (uint32_t*)(smf + KH0_OFF);
    uint32_t* KL0 = (uint32_t*)(smf + KL0_OFF);
    uint32_t* KH1 = (uint32_t*)(smf + KH1_OFF);
    uint32_t* KL1 = (uint32_t*)(smf + KL1_OFF);
    float*    Sp  = smf + SP_OFF;

    const int tid  = threadIdx.x;
    const int w    = tid >> 5;
    const int lane = tid & 31;
    const int gid  = lane >> 2;
    const int tg   = lane & 3;
    const int wm   = w & 7;        // column group (8 cols)
    const int mt   = w >> 3;       // row half
    const int bh = blockIdx.y, b = bh >> 2, h = bh & 3;
    const int n0 = blockIdx.x * 32;
    const int r0 = mt * 16 + gid;

    // staging indices (shared by all STS/LDG chunk ops)
    const int str  = tid >> 4;          // 0..31
    const int stc  = (tid & 15) * 4;    // 0..60
    const int str2 = (tid + 512) >> 4;  // 32..63

    // ---------- LDG Q (32x64 hi/lo) + emb chunk 0 ----------
    uint4 qh4, ql4, sh0, sh1, sl0, sl1;
    {
        const uint32_t* qh = g_qh + ((size_t)bh * N_ + n0) * C_;
        const uint32_t* ql = g_ql + ((size_t)bh * N_ + n0) * C_;
        qh4 = ((const uint4*)qh)[tid];
        ql4 = ((const uint4*)ql)[tid];
        const uint32_t* eh = g_eh + h * 64;
        const uint32_t* el = g_el + h * 64;
        sh0 = *(const uint4*)&eh[str * D_ + stc];
        sh1 = *(const uint4*)&eh[str2 * D_ + stc];
        sl0 = *(const uint4*)&el[str * D_ + stc];
        sl1 = *(const uint4*)&el[str2 * D_ + stc];
    }
    // stage Q through buffer 0
    *(uint4*)&KH0[str * KS_STRIDE + stc] = qh4;
    *(uint4*)&KL0[str * KS_STRIDE + stc] = ql4;
    __syncthreads();

    // ---------- preload Q hi+lo fragments into registers ----------
    uint32_t qfh[8][4], qfl[8][4];
#pragma unroll
    for (int kb = 0; kb < 8; kb++) {
        const int c0 = kb * 8 + tg;
        qfh[kb][0] = KH0[r0 * KS_STRIDE + c0];
        qfh[kb][1] = KH0[(r0 + 8) * KS_STRIDE + c0];
        qfh[kb][2] = KH0[r0 * KS_STRIDE + c0 + 4];
        qfh[kb][3] = KH0[(r0 + 8) * KS_STRIDE + c0 + 4];
        qfl[kb][0] = KL0[r0 * KS_STRIDE + c0];
        qfl[kb][1] = KL0[(r0 + 8) * KS_STRIDE + c0];
        qfl[kb][2] = KL0[r0 * KS_STRIDE + c0 + 4];
        qfl[kb][3] = KL0[(r0 + 8) * KS_STRIDE + c0 + 4];
    }
    __syncthreads();

    const uint32_t* kh_base = g_kh + (size_t)bh * M_ * C_;
    const uint32_t* kl_base = g_kl + (size_t)bh * M_ * C_;
    const uint32_t* vh_base = g_vh + (size_t)bh * M_ * C_;
    const uint32_t* vl_base = g_vl + (size_t)bh * M_ * C_;

    // ---------- SP phase: Sp(32x128) = Q · emb_h^T (2 chunks, dbl-buffered) ----------
#pragma unroll
    for (int pc = 0; pc < 2; pc++) {
        uint32_t* Khb = pc ? KH1 : KH0;
        uint32_t* Klb = pc ? KL1 : KL0;
        *(uint4*)&Khb[str * KS_STRIDE + stc]  = sh0;
        *(uint4*)&Khb[str2 * KS_STRIDE + stc] = sh1;
        *(uint4*)&Klb[str * KS_STRIDE + stc]  = sl0;
        *(uint4*)&Klb[str2 * KS_STRIDE + stc] = sl1;
        if (pc == 0) {   // prefetch emb chunk 1
            const uint32_t* eh = g_eh + 64 * D_ + h * 64;
            const uint32_t* el = g_el + 64 * D_ + h * 64;
            sh0 = *(const uint4*)&eh[str * D_ + stc];
            sh1 = *(const uint4*)&eh[str2 * D_ + stc];
            sl0 = *(const uint4*)&el[str * D_ + stc];
            sl1 = *(const uint4*)&el[str2 * D_ + stc];
        } else {         // prefetch K chunk 0
            sh0 = *(const uint4*)&kh_base[(size_t)tid * 4];
            sh1 = *(const uint4*)&kh_base[(size_t)(tid + 512) * 4];
            sl0 = *(const uint4*)&kl_base[(size_t)tid * 4];
            sl1 = *(const uint4*)&kl_base[(size_t)(tid + 512) * 4];
        }
        __syncthreads();

        float hh[4] = {}, hl[4] = {}, lh[4] = {};
#pragma unroll
        for (int kb = 0; kb < 8; kb++) {
            const int br = wm * 8 + gid, bc = kb * 8 + tg;
            uint32_t bhf[2] = {Khb[br * KS_STRIDE + bc], Khb[br * KS_STRIDE + bc + 4]};
            uint32_t blf[2] = {Klb[br * KS_STRIDE + bc], Klb[br * KS_STRIDE + bc + 4]};
            mma8(hh, qfh[kb], bhf);
            mma8(hl, qfh[kb], blf);
            mma8(lh, qfl[kb], bhf);
        }
        const int col = pc * 64 + wm * 8 + 2 * tg;
        *(float2*)(Sp + r0 * SP_STRIDE + col) =
            make_float2(hh[0] + hl[0] + lh[0], hh[1] + hl[1] + lh[1]);
        *(float2*)(Sp + (r0 + 8) * SP_STRIDE + col) =
            make_float2(hh[2] + hl[2] + lh[2], hh[3] + hl[3] + lh[3]);
    }

    // ---------- GEMM1: S(32x1024) = Q · K^T (16 chunks, 1 sync each) ----------
    for (int mc = 0; mc < 16; mc++) {
        uint32_t* Khb = (mc & 1) ? KH1 : KH0;
        uint32_t* Klb = (mc & 1) ? KL1 : KL0;
        *(uint4*)&Khb[str * KS_STRIDE + stc]  = sh0;
        *(uint4*)&Khb[str2 * KS_STRIDE + stc] = sh1;
        *(uint4*)&Klb[str * KS_STRIDE + stc]  = sl0;
        *(uint4*)&Klb[str2 * KS_STRIDE + stc] = sl1;
        if (mc < 15) {
            const size_t off = (size_t)(mc + 1) * 4096;
            sh0 = *(const uint4*)&kh_base[off + (size_t)tid * 4];
            sh1 = *(const uint4*)&kh_base[off + (size_t)(tid + 512) * 4];
            sl0 = *(const uint4*)&kl_base[off + (size_t)tid * 4];
            sl1 = *(const uint4*)&kl_base[off + (size_t)(tid + 512) * 4];
        }
        __syncthreads();

        float hh[4] = {}, hl[4] = {}, lh[4] = {};
#pragma unroll
        for (int kb = 0; kb < 8; kb++) {
            const int br = wm * 8 + gid, bc = kb * 8 + tg;
            uint32_t bhf[2] = {Khb[br * KS_STRIDE + bc], Khb[br * KS_STRIDE + bc + 4]};
            uint32_t blf[2] = {Klb[br * KS_STRIDE + bc], Klb[br * KS_STRIDE + bc + 4]};
            mma8(hh, qfh[kb], bhf);
            mma8(hl, qfh[kb], blf);
            mma8(lh, qfl[kb], bhf);
        }
        const int col = mc * 64 + wm * 8 + 2 * tg;
        *(float2*)(S + r0 * S_STRIDE + col) =
            make_float2(hh[0] + hl[0] + lh[0], hh[1] + hl[1] + lh[1]);
        *(float2*)(S + (r0 + 8) * S_STRIDE + col) =
            make_float2(hh[2] + hl[2] + lh[2], hh[3] + hl[3] + lh[3]);
    }
    __syncthreads();

    // prefetch V chunk 0 (overlaps epilogue + softmax)
    sh0 = *(const uint4*)&vh_base[(size_t)tid * 4];
    sh1 = *(const uint4*)&vh_base[(size_t)(tid + 512) * 4];
    sl0 = *(const uint4*)&vl_base[(size_t)tid * 4];
    sl1 = *(const uint4*)&vl_base[(size_t)(tid + 512) * 4];

    // ---------- epilogue: gather sp, factor, scale, mask ----------
    {
        const int half = tid >> 8, t2 = tid & 255;
        const int c4 = t2 * 4;
#pragma unroll 4
        for (int it = 0; it < 16; it++) {
            const int row = it * 2 + half;
            const size_t gbase = ((size_t)(b * N_ + n0 + row)) * M_ + c4;
            float4 sc = *(float4*)(S + row * S_STRIDE + c4);
            int4   id = *(const int4*)(eidx + gbase);
            float4 fa = *(const float4*)(factor + gbase);
            const float* sprow = Sp + row * SP_STRIDE;
            float e0 = fa.x * (sc.x + sprow[id.x]) * 0.125f;
            float e1 = fa.y * (sc.y + sprow[id.y]) * 0.125f;
            float e2 = fa.z * (sc.z + sprow[id.z]) * 0.125f;
            float e3 = fa.w * (sc.w + sprow[id.w]) * 0.125f;
            const unsigned char* km = kmask + b * M_ + c4;
            if (km[0]) e0 = -INFINITY;
            if (km[1]) e1 = -INFINITY;
            if (km[2]) e2 = -INFINITY;
            if (km[3]) e3 = -INFINITY;
            *(float4*)(S + row * S_STRIDE + c4) = make_float4(e0, e1, e2, e3);
        }
    }
    __syncthreads();

    // ---------- softmax: warp w owns rows 2w, 2w+1 ----------
#pragma unroll
    for (int rr = 0; rr < 2; rr++) {
        const int row = w * 2 + rr;
        float vals[32];
        float mx = -INFINITY;
#pragma unroll
        for (int j = 0; j < 8; j++) {
            float4 v = *(float4*)(S + row * S_STRIDE + (j * 32 + lane) * 4);
            vals[j * 4 + 0] = v.x; vals[j * 4 + 1] = v.y;
            vals[j * 4 + 2] = v.z; vals[j * 4 + 3] = v.w;
            mx = fmaxf(mx, fmaxf(fmaxf(v.x, v.y), fmaxf(v.z, v.w)));
        }
#pragma unroll
        for (int off = 16; off > 0; off >>= 1)
            mx = fmaxf(mx, __shfl_xor_sync(0xffffffffu, mx, off));
        float sum = 0.f;
#pragma unroll
        for (int i = 0; i < 32; i++) { vals[i] = __expf(vals[i] - mx); sum += vals[i]; }
#pragma unroll
        for (int off = 16; off > 0; off >>= 1)
            sum += __shfl_xor_sync(0xffffffffu, sum, off);
        const float inv = 1.0f / sum;
        const size_t abase = ((size_t)(bh * N_ + n0 + row)) * M_;
#pragma unroll
        for (int j = 0; j < 8; j++) {
            const int c4 = (j * 32 + lane) * 4;
            const float p0 = vals[j * 4 + 0] * inv, p1 = vals[j * 4 + 1] * inv;
            const float p2 = vals[j * 4 + 2] * inv, p3 = vals[j * 4 + 3] * inv;
            *(float4*)(attn + abase + c4) = make_float4(p0, p1, p2, p3);
            uint4 t = make_uint4(f2tf(p0), f2tf(p1), f2tf(p2), f2tf(p3));
            *(uint4*)(Su + row * S_STRIDE + c4) = t;
        }
    }

    // ---------- AV: hidden(32x64) = P · V (16 chunks, 1 sync each) ----------
    float avh[4] = {}, avl[4] = {};
    for (int kc = 0; kc < 16; kc++) {
        uint32_t* Khb = (kc & 1) ? KH1 : KH0;
        uint32_t* Klb = (kc & 1) ? KL1 : KL0;
        *(uint4*)&Khb[str * KS_STRIDE + stc]  = sh0;
        *(uint4*)&Khb[str2 * KS_STRIDE + stc] = sh1;
        *(uint4*)&Klb[str * KS_STRIDE + stc]  = sl0;
        *(uint4*)&Klb[str2 * KS_STRIDE + stc] = sl1;
        if (kc < 15) {
            const size_t off = (size_t)(kc + 1) * 4096;
            sh0 = *(const uint4*)&vh_base[off + (size_t)tid * 4];
            sh1 = *(const uint4*)&vh_base[off + (size_t)(tid + 512) * 4];
            sl0 = *(const uint4*)&vl_base[off + (size_t)tid * 4];
            sl1 = *(const uint4*)&vl_base[off + (size_t)(tid + 512) * 4];
        }
        __syncthreads();

#pragma unroll
        for (int kb = 0; kb < 8; kb++) {
            const int cbase = kc * 64 + kb * 8;
            uint32_t a[4];
            a[0] = Su[r0 * S_STRIDE + cbase + tg];
            a[1] = Su[(r0 + 8) * S_STRIDE + cbase + tg];
            a[2] = Su[r0 * S_STRIDE + cbase + tg + 4];
            a[3] = Su[(r0 + 8) * S_STRIDE + cbase + tg + 4];
            uint32_t bhf[2], blf[2];
            bhf[0] = Khb[(kb * 8 + tg) * KS_STRIDE + wm * 8 + gid];
            bhf[1] = Khb[(kb * 8 + tg + 4) * KS_STRIDE + wm * 8 + gid];
            blf[0] = Klb[(kb * 8 + tg) * KS_STRIDE + wm * 8 + gid];
            blf[1] = Klb[(kb * 8 + tg + 4) * KS_STRIDE + wm * 8 + gid];
            mma8(avh, a, bhf);
            mma8(avl, a, blf);
        }
    }

    // store hidden
    {
        const int row = n0 + r0;
        const int col = h * 64 + wm * 8 + 2 * tg;
        *(float2*)(hidden + ((size_t)b * N_ + row) * D_ + col) =
            make_float2(avh[0] + avl[0], avh[1] + avl[1]);
        *(float2*)(hidden + ((size_t)b * N_ + row + 8) * D_ + col) =
            make_float2(avh[2] + avl[2], avh[3] + avl[3]);
    }
}

// ============================================================================
// Launch
// ============================================================================
extern "C" void kernel_launch(void* const* d_in, const int* in_sizes, int n_in,
                              void* d_out, int out_size)
{
    const float* input_q = (const float*)d_in[0];
    const float* input_k = (const float*)d_in[1];
    const float* input_v = (const float*)d_in[2];
    const float* Wq = (const float*)d_in[3];
    const float* bq = (const float*)d_in[4];
    const float* Wk = (const float*)d_in[5];
    const float* bk = (const float*)d_in[6];
    const float* Wv = (const float*)d_in[7];
    const float* bv = (const float*)d_in[8];
    const float* emb_table = (const float*)d_in[9];
    const float* factor = (const float*)d_in[10];
    const int* eidx = (const int*)d_in[11];
    const unsigned char* kmask = (const unsigned char*)d_in[12];

    float* hidden = (float*)d_out;                          // (B,N,D)
    float* attn   = (float*)d_out + (size_t)B_ * N_ * D_;   // (B,H,N,M)

    static int smem_set = 0;
    if (!smem_set) {
        cudaFuncSetAttribute(fused_kernel,
                             cudaFuncAttributeMaxDynamicSharedMemorySize, SMEM_BYTES);
        smem_set = 1;
    }

    proj_kernel<<<dim3((B_ * N_) / 64, D_ / 64, 3), 256>>>(
        input_q, input_k, input_v, Wq, bq, Wk, bk, Wv, bv);

    emb_split_kernel<<<(P_ * D_) / 256, 256>>>(emb_table);

    fused_kernel<<<dim3(N_ / 32, B_ * H_), 512, SMEM_BYTES>>>(
        factor, eidx, kmask, attn, hidden);
}

// round 6
// speedup vs baseline: 1.1737x; 1.0222x over previous
#include <cuda_runtime.h>
#include <math.h>
#include <stdint.h>

#define B_ 8
#define N_ 1024
#define M_ 1024
#define D_ 256
#define H_ 4
#define P_ 128
#define C_ 64

// -------- device scratch: pre-split tf32 hi/lo operands --------
__device__ uint32_t g_qh[B_ * H_ * N_ * C_];
__device__ uint32_t g_ql[B_ * H_ * N_ * C_];
__device__ uint32_t g_kh[B_ * H_ * M_ * C_];
__device__ uint32_t g_kl[B_ * H_ * M_ * C_];
__device__ uint32_t g_vh[B_ * H_ * M_ * C_];
__device__ uint32_t g_vl[B_ * H_ * M_ * C_];
__device__ uint32_t g_eh[P_ * D_];
__device__ uint32_t g_el[P_ * D_];
__device__ uint32_t g_wsh[3 * D_ * D_];   // Wq|Wk|Wv hi
__device__ uint32_t g_wsl[3 * D_ * D_];   // Wq|Wk|Wv lo

// ---------------- tf32 helpers ----------------
__device__ __forceinline__ uint32_t f2tf(float x) {
    uint32_t u;
    asm("cvt.rna.tf32.f32 %0, %1;" : "=r"(u) : "f"(x));
    return u;
}

__device__ __forceinline__ void mma8(float d[4], const uint32_t a[4], const uint32_t b[2]) {
    asm volatile(
        "mma.sync.aligned.m16n8k8.row.col.f32.tf32.tf32.f32 "
        "{%0,%1,%2,%3}, {%4,%5,%6,%7}, {%8,%9}, {%0,%1,%2,%3};"
        : "+f"(d[0]), "+f"(d[1]), "+f"(d[2]), "+f"(d[3])
        : "r"(a[0]), "r"(a[1]), "r"(a[2]), "r"(a[3]), "r"(b[0]), "r"(b[1]));
}

// ---------------- fused-kernel smem layout (float units) ----------------
#define S_STRIDE  1036
#define KS_STRIDE 76
#define KH0_OFF   33152
#define KL0_OFF   38016
#define KH1_OFF   42880
#define KL1_OFF   47744
#define SP_STRIDE 132
#define SP_OFF    52608
#define SMEM_FLOATS 56832
#define SMEM_BYTES  (SMEM_FLOATS * 4)  // 227328 B

// ============================================================================
// Kernel 0: split Wq/Wk/Wv and emb_table into tf32 hi/lo (runs once per call).
// elems: 32768 emb + 3*65536 W = 229376 -> 896 blocks x 256.
// ============================================================================
__global__ __launch_bounds__(256) void split_kernel(
    const float* __restrict__ emb, const float* __restrict__ Wq,
    const float* __restrict__ Wk, const float* __restrict__ Wv)
{
    const int i = blockIdx.x * 256 + threadIdx.x;
    float v;
    uint32_t *oh, *ol;
    int idx;
    if (i < P_ * D_) {
        v = emb[i]; oh = g_eh; ol = g_el; idx = i;
    } else {
        const int j = i - P_ * D_;
        const int which = j >> 16;
        const int jj = j & 65535;
        const float* W = (which == 0) ? Wq : (which == 1) ? Wk : Wv;
        v = W[jj]; oh = g_wsh; ol = g_wsl; idx = j;
    }
    const uint32_t hi = f2tf(v);
    oh[idx] = hi;
    ol[idx] = f2tf(v - __uint_as_float(hi));
}

// ============================================================================
// Kernel 1: QKV projection on tensor cores (split tf32, 3-MMA).
//   out[b,h,l,c] = sum_d X[b,l,d]*W[h*C+c,d] + bias  -> written as tf32 hi/lo.
// 64x64 tile, 256 thr (8 warps: wr=w&3 row group, wc=w>>2 col group),
// K=256 in 16 chunks, double-buffered, 1 barrier per chunk.
// ============================================================================
#define PJ_STRIDE 20
__global__ __launch_bounds__(256, 2) void proj_kernel(
    const float* __restrict__ Xq, const float* __restrict__ Xk,
    const float* __restrict__ Xv,
    const float* __restrict__ bq, const float* __restrict__ bk,
    const float* __restrict__ bv)
{
    const int which = blockIdx.z;
    const float* X    = (which == 0) ? Xq : (which == 1) ? Xk : Xv;
    const float* bias = (which == 0) ? bq : (which == 1) ? bk : bv;
    uint32_t* outh    = (which == 0) ? g_qh : (which == 1) ? g_kh : g_vh;
    uint32_t* outl    = (which == 0) ? g_ql : (which == 1) ? g_kl : g_vl;
    const uint32_t* wh_base = g_wsh + which * D_ * D_;
    const uint32_t* wl_base = g_wsl + which * D_ * D_;

    const int r0 = blockIdx.x * 64;   // rows over B*N = 8192
    const int j0 = blockIdx.y * 64;   // cols over D = 256

    // double-buffered staging: [buf][64][20] for Xh, Xl, Wh, Wl
    __shared__ uint32_t Xh[2][64 * PJ_STRIDE], Xl[2][64 * PJ_STRIDE];
    __shared__ uint32_t Wh[2][64 * PJ_STRIDE], Wl[2][64 * PJ_STRIDE];

    const int tid  = threadIdx.x;
    const int w    = tid >> 5;
    const int lane = tid & 31;
    const int gid  = lane >> 2;
    const int tg   = lane & 3;
    const int wr   = w & 3;           // row group: rows wr*16 + gid (+8)
    const int wc   = w >> 2;          // col group: cols wc*32 + ns*8
    const int ar0  = wr * 16 + gid;

    const int srow = tid >> 2;        // 0..63
    const int sc4  = (tid & 3) * 4;   // 0,4,8,12

    // prefetch chunk 0
    float4 xv = *(const float4*)&X[(size_t)(r0 + srow) * D_ + sc4];
    uint4  wh = *(const uint4*)&wh_base[(size_t)(j0 + srow) * D_ + sc4];
    uint4  wl = *(const uint4*)&wl_base[(size_t)(j0 + srow) * D_ + sc4];

    float hh[4][4] = {}, hl[4][4] = {}, lh[4][4] = {};

    for (int mc = 0; mc < 16; mc++) {
        const int bsel = mc & 1;
        // STS current chunk (convert X to hi/lo in-register)
        {
            float xs[4] = {xv.x, xv.y, xv.z, xv.w};
            uint32_t xh4[4], xl4[4];
#pragma unroll
            for (int e = 0; e < 4; e++) {
                xh4[e] = f2tf(xs[e]);
                xl4[e] = f2tf(xs[e] - __uint_as_float(xh4[e]));
            }
            *(uint4*)&Xh[bsel][srow * PJ_STRIDE + sc4] = make_uint4(xh4[0], xh4[1], xh4[2], xh4[3]);
            *(uint4*)&Xl[bsel][srow * PJ_STRIDE + sc4] = make_uint4(xl4[0], xl4[1], xl4[2], xl4[3]);
            *(uint4*)&Wh[bsel][srow * PJ_STRIDE + sc4] = wh;
            *(uint4*)&Wl[bsel][srow * PJ_STRIDE + sc4] = wl;
        }
        if (mc < 15) {   // prefetch next chunk (overlaps MMA below)
            const int kc = (mc + 1) * 16;
            xv = *(const float4*)&X[(size_t)(r0 + srow) * D_ + kc + sc4];
            wh = *(const uint4*)&wh_base[(size_t)(j0 + srow) * D_ + kc + sc4];
            wl = *(const uint4*)&wl_base[(size_t)(j0 + srow) * D_ + kc + sc4];
        }
        __syncthreads();

        const uint32_t* xhb = Xh[bsel];
        const uint32_t* xlb = Xl[bsel];
        const uint32_t* whb = Wh[bsel];
        const uint32_t* wlb = Wl[bsel];
#pragma unroll
        for (int kb = 0; kb < 2; kb++) {
            const int c0 = kb * 8 + tg;
            uint32_t ah[4], al[4];
            ah[0] = xhb[ar0 * PJ_STRIDE + c0];
            ah[1] = xhb[(ar0 + 8) * PJ_STRIDE + c0];
            ah[2] = xhb[ar0 * PJ_STRIDE + c0 + 4];
            ah[3] = xhb[(ar0 + 8) * PJ_STRIDE + c0 + 4];
            al[0] = xlb[ar0 * PJ_STRIDE + c0];
            al[1] = xlb[(ar0 + 8) * PJ_STRIDE + c0];
            al[2] = xlb[ar0 * PJ_STRIDE + c0 + 4];
            al[3] = xlb[(ar0 + 8) * PJ_STRIDE + c0 + 4];
#pragma unroll
            for (int ns = 0; ns < 4; ns++) {
                const int br = wc * 32 + ns * 8 + gid;
                uint32_t bhf[2] = {whb[br * PJ_STRIDE + c0], whb[br * PJ_STRIDE + c0 + 4]};
                uint32_t blf[2] = {wlb[br * PJ_STRIDE + c0], wlb[br * PJ_STRIDE + c0 + 4]};
                mma8(hh[ns], ah, bhf);
                mma8(hl[ns], ah, blf);
                mma8(lh[ns], al, bhf);
            }
        }
        __syncthreads();
    }

    // epilogue: combine splits, add bias, re-split to tf32 hi/lo, store
#pragma unroll
    for (int ns = 0; ns < 4; ns++) {
        const int col = j0 + wc * 32 + ns * 8 + 2 * tg;
        const float b0 = bias[col], b1 = bias[col + 1];
        const int h = col >> 6, c = col & 63;
#pragma unroll
        for (int half = 0; half < 2; half++) {
            const int r = r0 + wr * 16 + gid + half * 8;
            const int bb = r >> 10, l = r & 1023;
            const size_t idx = (((size_t)(bb * H_ + h) * N_) + l) * C_ + c;
            const float v0 = hh[ns][half * 2 + 0] + hl[ns][half * 2 + 0] + lh[ns][half * 2 + 0] + b0;
            const float v1 = hh[ns][half * 2 + 1] + hl[ns][half * 2 + 1] + lh[ns][half * 2 + 1] + b1;
            const uint32_t h0 = f2tf(v0), h1 = f2tf(v1);
            *(uint2*)&outh[idx] = make_uint2(h0, h1);
            *(uint2*)&outl[idx] = make_uint2(f2tf(v0 - __uint_as_float(h0)),
                                             f2tf(v1 - __uint_as_float(h1)));
        }
    }
}

// ============================================================================
// Kernel 2: FUSED sp + scores + gather/factor/mask + softmax + attn + AV.
// (unchanged from R5 — 512 thr, double-buffered, Q frags in registers)
// ============================================================================
__global__ __launch_bounds__(512, 1) void fused_kernel(
    const float* __restrict__ factor, const int* __restrict__ eidx,
    const unsigned char* __restrict__ kmask,
    float* __restrict__ attn, float* __restrict__ hidden)
{
    extern __shared__ float smf[];
    float*    S   = smf;
    uint32_t* Su  = (uint32_t*)smf;
    uint32_t* KH0 = (uint32_t*)(smf + KH0_OFF);
    uint32_t* KL0 = (uint32_t*)(smf + KL0_OFF);
    uint32_t* KH1 = (uint32_t*)(smf + KH1_OFF);
    uint32_t* KL1 = (uint32_t*)(smf + KL1_OFF);
    float*    Sp  = smf + SP_OFF;

    const int tid  = threadIdx.x;
    const int w    = tid >> 5;
    const int lane = tid & 31;
    const int gid  = lane >> 2;
    const int tg   = lane & 3;
    const int wm   = w & 7;
    const int mt   = w >> 3;
    const int bh = blockIdx.y, b = bh >> 2, h = bh & 3;
    const int n0 = blockIdx.x * 32;
    const int r0 = mt * 16 + gid;

    const int str  = tid >> 4;
    const int stc  = (tid & 15) * 4;
    const int str2 = (tid + 512) >> 4;

    uint4 qh4, ql4, sh0, sh1, sl0, sl1;
    {
        const uint32_t* qh = g_qh + ((size_t)bh * N_ + n0) * C_;
        const uint32_t* ql = g_ql + ((size_t)bh * N_ + n0) * C_;
        qh4 = ((const uint4*)qh)[tid];
        ql4 = ((const uint4*)ql)[tid];
        const uint32_t* eh = g_eh + h * 64;
        const uint32_t* el = g_el + h * 64;
        sh0 = *(const uint4*)&eh[str * D_ + stc];
        sh1 = *(const uint4*)&eh[str2 * D_ + stc];
        sl0 = *(const uint4*)&el[str * D_ + stc];
        sl1 = *(const uint4*)&el[str2 * D_ + stc];
    }
    *(uint4*)&KH0[str * KS_STRIDE + stc] = qh4;
    *(uint4*)&KL0[str * KS_STRIDE + stc] = ql4;
    __syncthreads();

    uint32_t qfh[8][4], qfl[8][4];
#pragma unroll
    for (int kb = 0; kb < 8; kb++) {
        const int c0 = kb * 8 + tg;
        qfh[kb][0] = KH0[r0 * KS_STRIDE + c0];
        qfh[kb][1] = KH0[(r0 + 8) * KS_STRIDE + c0];
        qfh[kb][2] = KH0[r0 * KS_STRIDE + c0 + 4];
        qfh[kb][3] = KH0[(r0 + 8) * KS_STRIDE + c0 + 4];
        qfl[kb][0] = KL0[r0 * KS_STRIDE + c0];
        qfl[kb][1] = KL0[(r0 + 8) * KS_STRIDE + c0];
        qfl[kb][2] = KL0[r0 * KS_STRIDE + c0 + 4];
        qfl[kb][3] = KL0[(r0 + 8) * KS_STRIDE + c0 + 4];
    }
    __syncthreads();

    const uint32_t* kh_base = g_kh + (size_t)bh * M_ * C_;
    const uint32_t* kl_base = g_kl + (size_t)bh * M_ * C_;
    const uint32_t* vh_base = g_vh + (size_t)bh * M_ * C_;
    const uint32_t* vl_base = g_vl + (size_t)bh * M_ * C_;

#pragma unroll
    for (int pc = 0; pc < 2; pc++) {
        uint32_t* Khb = pc ? KH1 : KH0;
        uint32_t* Klb = pc ? KL1 : KL0;
        *(uint4*)&Khb[str * KS_STRIDE + stc]  = sh0;
        *(uint4*)&Khb[str2 * KS_STRIDE + stc] = sh1;
        *(uint4*)&Klb[str * KS_STRIDE + stc]  = sl0;
        *(uint4*)&Klb[str2 * KS_STRIDE + stc] = sl1;
        if (pc == 0) {
            const uint32_t* eh = g_eh + 64 * D_ + h * 64;
            const uint32_t* el = g_el + 64 * D_ + h * 64;
            sh0 = *(const uint4*)&eh[str * D_ + stc];
            sh1 = *(const uint4*)&eh[str2 * D_ + stc];
            sl0 = *(const uint4*)&el[str * D_ + stc];
            sl1 = *(const uint4*)&el[str2 * D_ + stc];
        } else {
            sh0 = *(const uint4*)&kh_base[(size_t)tid * 4];
            sh1 = *(const uint4*)&kh_base[(size_t)(tid + 512) * 4];
            sl0 = *(const uint4*)&kl_base[(size_t)tid * 4];
            sl1 = *(const uint4*)&kl_base[(size_t)(tid + 512) * 4];
        }
        __syncthreads();

        float hh[4] = {}, hl[4] = {}, lh[4] = {};
#pragma unroll
        for (int kb = 0; kb < 8; kb++) {
            const int br = wm * 8 + gid, bc = kb * 8 + tg;
            uint32_t bhf[2] = {Khb[br * KS_STRIDE + bc], Khb[br * KS_STRIDE + bc + 4]};
            uint32_t blf[2] = {Klb[br * KS_STRIDE + bc], Klb[br * KS_STRIDE + bc + 4]};
            mma8(hh, qfh[kb], bhf);
            mma8(hl, qfh[kb], blf);
            mma8(lh, qfl[kb], bhf);
        }
        const int col = pc * 64 + wm * 8 + 2 * tg;
        *(float2*)(Sp + r0 * SP_STRIDE + col) =
            make_float2(hh[0] + hl[0] + lh[0], hh[1] + hl[1] + lh[1]);
        *(float2*)(Sp + (r0 + 8) * SP_STRIDE + col) =
            make_float2(hh[2] + hl[2] + lh[2], hh[3] + hl[3] + lh[3]);
    }

    for (int mc = 0; mc < 16; mc++) {
        uint32_t* Khb = (mc & 1) ? KH1 : KH0;
        uint32_t* Klb = (mc & 1) ? KL1 : KL0;
        *(uint4*)&Khb[str * KS_STRIDE + stc]  = sh0;
        *(uint4*)&Khb[str2 * KS_STRIDE + stc] = sh1;
        *(uint4*)&Klb[str * KS_STRIDE + stc]  = sl0;
        *(uint4*)&Klb[str2 * KS_STRIDE + stc] = sl1;
        if (mc < 15) {
            const size_t off = (size_t)(mc + 1) * 4096;
            sh0 = *(const uint4*)&kh_base[off + (size_t)tid * 4];
            sh1 = *(const uint4*)&kh_base[off + (size_t)(tid + 512) * 4];
            sl0 = *(const uint4*)&kl_base[off + (size_t)tid * 4];
            sl1 = *(const uint4*)&kl_base[off + (size_t)(tid + 512) * 4];
        }
        __syncthreads();

        float hh[4] = {}, hl[4] = {}, lh[4] = {};
#pragma unroll
        for (int kb = 0; kb < 8; kb++) {
            const int br = wm * 8 + gid, bc = kb * 8 + tg;
            uint32_t bhf[2] = {Khb[br * KS_STRIDE + bc], Khb[br * KS_STRIDE + bc + 4]};
            uint32_t blf[2] = {Klb[br * KS_STRIDE + bc], Klb[br * KS_STRIDE + bc + 4]};
            mma8(hh, qfh[kb], bhf);
            mma8(hl, qfh[kb], blf);
            mma8(lh, qfl[kb], bhf);
        }
        const int col = mc * 64 + wm * 8 + 2 * tg;
        *(float2*)(S + r0 * S_STRIDE + col) =
            make_float2(hh[0] + hl[0] + lh[0], hh[1] + hl[1] + lh[1]);
        *(float2*)(S + (r0 + 8) * S_STRIDE + col) =
            make_float2(hh[2] + hl[2] + lh[2], hh[3] + hl[3] + lh[3]);
    }
    __syncthreads();

    sh0 = *(const uint4*)&vh_base[(size_t)tid * 4];
    sh1 = *(const uint4*)&vh_base[(size_t)(tid + 512) * 4];
    sl0 = *(const uint4*)&vl_base[(size_t)tid * 4];
    sl1 = *(const uint4*)&vl_base[(size_t)(tid + 512) * 4];

    {
        const int half = tid >> 8, t2 = tid & 255;
        const int c4 = t2 * 4;
#pragma unroll 4
        for (int it = 0; it < 16; it++) {
            const int row = it * 2 + half;
            const size_t gbase = ((size_t)(b * N_ + n0 + row)) * M_ + c4;
            float4 sc = *(float4*)(S + row * S_STRIDE + c4);
            int4   id = *(const int4*)(eidx + gbase);
            float4 fa = *(const float4*)(factor + gbase);
            const float* sprow = Sp + row * SP_STRIDE;
            float e0 = fa.x * (sc.x + sprow[id.x]) * 0.125f;
            float e1 = fa.y * (sc.y + sprow[id.y]) * 0.125f;
            float e2 = fa.z * (sc.z + sprow[id.z]) * 0.125f;
            float e3 = fa.w * (sc.w + sprow[id.w]) * 0.125f;
            const unsigned char* km = kmask + b * M_ + c4;
            if (km[0]) e0 = -INFINITY;
            if (km[1]) e1 = -INFINITY;
            if (km[2]) e2 = -INFINITY;
            if (km[3]) e3 = -INFINITY;
            *(float4*)(S + row * S_STRIDE + c4) = make_float4(e0, e1, e2, e3);
        }
    }
    __syncthreads();

#pragma unroll
    for (int rr = 0; rr < 2; rr++) {
        const int row = w * 2 + rr;
        float vals[32];
        float mx = -INFINITY;
#pragma unroll
        for (int j = 0; j < 8; j++) {
            float4 v = *(float4*)(S + row * S_STRIDE + (j * 32 + lane) * 4);
            vals[j * 4 + 0] = v.x; vals[j * 4 + 1] = v.y;
            vals[j * 4 + 2] = v.z; vals[j * 4 + 3] = v.w;
            mx = fmaxf(mx, fmaxf(fmaxf(v.x, v.y), fmaxf(v.z, v.w)));
        }
#pragma unroll
        for (int off = 16; off > 0; off >>= 1)
            mx = fmaxf(mx, __shfl_xor_sync(0xffffffffu, mx, off));
        float sum = 0.f;
#pragma unroll
        for (int i = 0; i < 32; i++) { vals[i] = __expf(vals[i] - mx); sum += vals[i]; }
#pragma unroll
        for (int off = 16; off > 0; off >>= 1)
            sum += __shfl_xor_sync(0xffffffffu, sum, off);
        const float inv = 1.0f / sum;
        const size_t abase = ((size_t)(bh * N_ + n0 + row)) * M_;
#pragma unroll
        for (int j = 0; j < 8; j++) {
            const int c4 = (j * 32 + lane) * 4;
            const float p0 = vals[j * 4 + 0] * inv, p1 = vals[j * 4 + 1] * inv;
            const float p2 = vals[j * 4 + 2] * inv, p3 = vals[j * 4 + 3] * inv;
            *(float4*)(attn + abase + c4) = make_float4(p0, p1, p2, p3);
            uint4 t = make_uint4(f2tf(p0), f2tf(p1), f2tf(p2), f2tf(p3));
            *(uint4*)(Su + row * S_STRIDE + c4) = t;
        }
    }

    float avh[4] = {}, avl[4] = {};
    for (int kc = 0; kc < 16; kc++) {
        uint32_t* Khb = (kc & 1) ? KH1 : KH0;
        uint32_t* Klb = (kc & 1) ? KL1 : KL0;
        *(uint4*)&Khb[str * KS_STRIDE + stc]  = sh0;
        *(uint4*)&Khb[str2 * KS_STRIDE + stc] = sh1;
        *(uint4*)&Klb[str * KS_STRIDE + stc]  = sl0;
        *(uint4*)&Klb[str2 * KS_STRIDE + stc] = sl1;
        if (kc < 15) {
            const size_t off = (size_t)(kc + 1) * 4096;
            sh0 = *(const uint4*)&vh_base[off + (size_t)tid * 4];
            sh1 = *(const uint4*)&vh_base[off + (size_t)(tid + 512) * 4];
            sl0 = *(const uint4*)&vl_base[off + (size_t)tid * 4];
            sl1 = *(const uint4*)&vl_base[off + (size_t)(tid + 512) * 4];
        }
        __syncthreads();

#pragma unroll
        for (int kb = 0; kb < 8; kb++) {
            const int cbase = kc * 64 + kb * 8;
            uint32_t a[4];
            a[0] = Su[r0 * S_STRIDE + cbase + tg];
            a[1] = Su[(r0 + 8) * S_STRIDE + cbase + tg];
            a[2] = Su[r0 * S_STRIDE + cbase + tg + 4];
            a[3] = Su[(r0 + 8) * S_STRIDE + cbase + tg + 4];
            uint32_t bhf[2], blf[2];
            bhf[0] = Khb[(kb * 8 + tg) * KS_STRIDE + wm * 8 + gid];
            bhf[1] = Khb[(kb * 8 + tg + 4) * KS_STRIDE + wm * 8 + gid];
            blf[0] = Klb[(kb * 8 + tg) * KS_STRIDE + wm * 8 + gid];
            blf[1] = Klb[(kb * 8 + tg + 4) * KS_STRIDE + wm * 8 + gid];
            mma8(avh, a, bhf);
            mma8(avl, a, blf);
        }
    }

    {
        const int row = n0 + r0;
        const int col = h * 64 + wm * 8 + 2 * tg;
        *(float2*)(hidden + ((size_t)b * N_ + row) * D_ + col) =
            make_float2(avh[0] + avl[0], avh[1] + avl[1]);
        *(float2*)(hidden + ((size_t)b * N_ + row + 8) * D_ + col) =
            make_float2(avh[2] + avl[2], avh[3] + avl[3]);
    }
}

// ============================================================================
// Launch
// ============================================================================
extern "C" void kernel_launch(void* const* d_in, const int* in_sizes, int n_in,
                              void* d_out, int out_size)
{
    const float* input_q = (const float*)d_in[0];
    const float* input_k = (const float*)d_in[1];
    const float* input_v = (const float*)d_in[2];
    const float* Wq = (const float*)d_in[3];
    const float* bq = (const float*)d_in[4];
    const float* Wk = (const float*)d_in[5];
    const float* bk = (const float*)d_in[6];
    const float* Wv = (const float*)d_in[7];
    const float* bv = (const float*)d_in[8];
    const float* emb_table = (const float*)d_in[9];
    const float* factor = (const float*)d_in[10];
    const int* eidx = (const int*)d_in[11];
    const unsigned char* kmask = (const unsigned char*)d_in[12];

    float* hidden = (float*)d_out;                          // (B,N,D)
    float* attn   = (float*)d_out + (size_t)B_ * N_ * D_;   // (B,H,N,M)

    static int smem_set = 0;
    if (!smem_set) {
        cudaFuncSetAttribute(fused_kernel,
                             cudaFuncAttributeMaxDynamicSharedMemorySize, SMEM_BYTES);
        smem_set = 1;
    }

    split_kernel<<<(P_ * D_ + 3 * D_ * D_) / 256, 256>>>(emb_table, Wq, Wk, Wv);

    proj_kernel<<<dim3((B_ * N_) / 64, D_ / 64, 3), 256>>>(
        input_q, input_k, input_v, bq, bk, bv);

    fused_kernel<<<dim3(N_ / 32, B_ * H_), 512, SMEM_BYTES>>>(
        factor, eidx, kmask, attn, hidden);
}

// round 7
// speedup vs baseline: 1.9131x; 1.6300x over previous
#include <cuda_runtime.h>
#include <cuda_bf16.h>
#include <math.h>
#include <stdint.h>

#define B_ 8
#define N_ 1024
#define M_ 1024
#define D_ 256
#define H_ 4
#define P_ 128
#define C_ 64
#define CP_ 32   // C/2 pairs

// -------- device scratch: bf16x2-packed hi/lo operands (pairs along K dim) --------
__device__ uint32_t g_qh[B_ * H_ * N_ * CP_];
__device__ uint32_t g_ql[B_ * H_ * N_ * CP_];
__device__ uint32_t g_kh[B_ * H_ * M_ * CP_];
__device__ uint32_t g_kl[B_ * H_ * M_ * CP_];
__device__ uint32_t g_vh[B_ * H_ * M_ * CP_];
__device__ uint32_t g_vl[B_ * H_ * M_ * CP_];
__device__ uint32_t g_eh[P_ * D_ / 2];
__device__ uint32_t g_el[P_ * D_ / 2];
__device__ uint32_t g_wsh[3 * D_ * D_ / 2];
__device__ uint32_t g_wsl[3 * D_ * D_ / 2];

// ---------------- helpers ----------------
__device__ __forceinline__ void split2(float v0, float v1, uint32_t& hp, uint32_t& lp) {
    __nv_bfloat16 h0 = __float2bfloat16_rn(v0);
    __nv_bfloat16 h1 = __float2bfloat16_rn(v1);
    __nv_bfloat16 l0 = __float2bfloat16_rn(v0 - __bfloat162float(h0));
    __nv_bfloat16 l1 = __float2bfloat16_rn(v1 - __bfloat162float(h1));
    hp = (uint32_t)__bfloat16_as_ushort(h0) | ((uint32_t)__bfloat16_as_ushort(h1) << 16);
    lp = (uint32_t)__bfloat16_as_ushort(l0) | ((uint32_t)__bfloat16_as_ushort(l1) << 16);
}

__device__ __forceinline__ uint32_t pack2(float v0, float v1) {
    __nv_bfloat16 b0 = __float2bfloat16_rn(v0);
    __nv_bfloat16 b1 = __float2bfloat16_rn(v1);
    return (uint32_t)__bfloat16_as_ushort(b0) | ((uint32_t)__bfloat16_as_ushort(b1) << 16);
}

__device__ __forceinline__ uint32_t prmtb(uint32_t a, uint32_t b, uint32_t sel) {
    uint32_t r;
    asm("prmt.b32 %0, %1, %2, %3;" : "=r"(r) : "r"(a), "r"(b), "r"(sel));
    return r;
}

__device__ __forceinline__ void mma16(float d[4], const uint32_t a[4], const uint32_t b[2]) {
    asm volatile(
        "mma.sync.aligned.m16n8k16.row.col.f32.bf16.bf16.f32 "
        "{%0,%1,%2,%3}, {%4,%5,%6,%7}, {%8,%9}, {%0,%1,%2,%3};"
        : "+f"(d[0]), "+f"(d[1]), "+f"(d[2]), "+f"(d[3])
        : "r"(a[0]), "r"(a[1]), "r"(a[2]), "r"(a[3]), "r"(b[0]), "r"(b[1]));
}

// ---------------- fused smem layout (32-bit words) ----------------
#define S_STRIDE  1036   // fp32 logits; packed probs live inside each row: hi [0,512), lo [518,1030)
#define KB_STRIDE 36     // K/Q/emb staging: 64 rows x 32 pairs (+4 pad)
#define VB_STRIDE 72     // V staging (pair-along-M): 32 mp x 64 cols (+8 pad)
#define KH0_OFF   33152
#define KL0_OFF   35456
#define KH1_OFF   37760
#define KL1_OFF   40064
#define VH0_OFF   42368
#define VL0_OFF   44672
#define VH1_OFF   46976
#define VL1_OFF   49280
#define SP_STRIDE 132
#define SP_OFF    51584
#define SMEM_WORDS 55808
#define SMEM_BYTES (SMEM_WORDS * 4)   // 223232 B

// ============================================================================
// Kernel 0: split W/emb into packed bf16x2 hi/lo pairs (along d).
// 114688 pairs total: 16384 emb + 3*32768 W.
// ============================================================================
__global__ __launch_bounds__(256) void split_kernel(
    const float* __restrict__ emb, const float* __restrict__ Wq,
    const float* __restrict__ Wk, const float* __restrict__ Wv)
{
    const int i = blockIdx.x * 256 + threadIdx.x;
    float v0, v1;
    uint32_t *oh, *ol;
    int idx;
    if (i < P_ * D_ / 2) {
        v0 = emb[2 * i]; v1 = emb[2 * i + 1]; oh = g_eh; ol = g_el; idx = i;
    } else {
        const int j = i - P_ * D_ / 2;
        const int which = j >> 15;
        const int jj = j & 32767;
        const float* W = (which == 0) ? Wq : (which == 1) ? Wk : Wv;
        v0 = W[2 * jj]; v1 = W[2 * jj + 1]; oh = g_wsh; ol = g_wsl; idx = j;
    }
    uint32_t hp, lp;
    split2(v0, v1, hp, lp);
    oh[idx] = hp;
    ol[idx] = lp;
}

// ============================================================================
// Kernel 1: QKV projection, split-bf16 m16n8k16 (3-MMA).
// 64x64 tile, 256 thr, K=256 in 8 chunks of 32, double-buffered.
// ============================================================================
#define PJ_STRIDE 20
__global__ __launch_bounds__(256, 2) void proj_kernel(
    const float* __restrict__ Xq, const float* __restrict__ Xk,
    const float* __restrict__ Xv,
    const float* __restrict__ bq, const float* __restrict__ bk,
    const float* __restrict__ bv)
{
    const int which = blockIdx.z;
    const float* X    = (which == 0) ? Xq : (which == 1) ? Xk : Xv;
    const float* bias = (which == 0) ? bq : (which == 1) ? bk : bv;
    uint32_t* outh    = (which == 0) ? g_qh : (which == 1) ? g_kh : g_vh;
    uint32_t* outl    = (which == 0) ? g_ql : (which == 1) ? g_kl : g_vl;
    const uint32_t* wh_base = g_wsh + which * (D_ * D_ / 2);
    const uint32_t* wl_base = g_wsl + which * (D_ * D_ / 2);

    const int r0 = blockIdx.x * 64;
    const int j0 = blockIdx.y * 64;

    __shared__ uint32_t Xh[2][64 * PJ_STRIDE], Xl[2][64 * PJ_STRIDE];
    __shared__ uint32_t Wh[2][64 * PJ_STRIDE], Wl[2][64 * PJ_STRIDE];

    const int tid  = threadIdx.x;
    const int w    = tid >> 5;
    const int lane = tid & 31;
    const int gid  = lane >> 2;
    const int tg   = lane & 3;
    const int wr   = w & 3;
    const int wc   = w >> 2;
    const int ar0  = wr * 16 + gid;

    const int srow = tid >> 2;        // 0..63
    const int sc   = tid & 3;         // 0..3

    // prefetch chunk 0: X 8 floats (2 float4), W 1 uint4 per array
    float4 xa = *(const float4*)&X[(size_t)(r0 + srow) * D_ + sc * 8];
    float4 xb = *(const float4*)&X[(size_t)(r0 + srow) * D_ + sc * 8 + 4];
    uint4  wh = *(const uint4*)&wh_base[(size_t)(j0 + srow) * (D_ / 2) + sc * 4];
    uint4  wl = *(const uint4*)&wl_base[(size_t)(j0 + srow) * (D_ / 2) + sc * 4];

    float hh[4][4] = {}, hl[4][4] = {}, lh[4][4] = {};

    for (int mc = 0; mc < 8; mc++) {
        const int bsel = mc & 1;
        {   // convert X to packed hi/lo, STS everything
            uint4 xh4, xl4;
            split2(xa.x, xa.y, xh4.x, xl4.x);
            split2(xa.z, xa.w, xh4.y, xl4.y);
            split2(xb.x, xb.y, xh4.z, xl4.z);
            split2(xb.z, xb.w, xh4.w, xl4.w);
            *(uint4*)&Xh[bsel][srow * PJ_STRIDE + sc * 4] = xh4;
            *(uint4*)&Xl[bsel][srow * PJ_STRIDE + sc * 4] = xl4;
            *(uint4*)&Wh[bsel][srow * PJ_STRIDE + sc * 4] = wh;
            *(uint4*)&Wl[bsel][srow * PJ_STRIDE + sc * 4] = wl;
        }
        if (mc < 7) {
            const int kc = (mc + 1) * 32;
            xa = *(const float4*)&X[(size_t)(r0 + srow) * D_ + kc + sc * 8];
            xb = *(const float4*)&X[(size_t)(r0 + srow) * D_ + kc + sc * 8 + 4];
            wh = *(const uint4*)&wh_base[(size_t)(j0 + srow) * (D_ / 2) + kc / 2 + sc * 4];
            wl = *(const uint4*)&wl_base[(size_t)(j0 + srow) * (D_ / 2) + kc / 2 + sc * 4];
        }
        __syncthreads();

        const uint32_t* xhb = Xh[bsel];
        const uint32_t* xlb = Xl[bsel];
        const uint32_t* whb = Wh[bsel];
        const uint32_t* wlb = Wl[bsel];
#pragma unroll
        for (int kb = 0; kb < 2; kb++) {
            const int c0 = kb * 8 + tg;
            uint32_t ah[4], al[4];
            ah[0] = xhb[ar0 * PJ_STRIDE + c0];
            ah[1] = xhb[(ar0 + 8) * PJ_STRIDE + c0];
            ah[2] = xhb[ar0 * PJ_STRIDE + c0 + 4];
            ah[3] = xhb[(ar0 + 8) * PJ_STRIDE + c0 + 4];
            al[0] = xlb[ar0 * PJ_STRIDE + c0];
            al[1] = xlb[(ar0 + 8) * PJ_STRIDE + c0];
            al[2] = xlb[ar0 * PJ_STRIDE + c0 + 4];
            al[3] = xlb[(ar0 + 8) * PJ_STRIDE + c0 + 4];
#pragma unroll
            for (int ns = 0; ns < 4; ns++) {
                const int br = wc * 32 + ns * 8 + gid;
                uint32_t bhf[2] = {whb[br * PJ_STRIDE + c0], whb[br * PJ_STRIDE + c0 + 4]};
                uint32_t blf[2] = {wlb[br * PJ_STRIDE + c0], wlb[br * PJ_STRIDE + c0 + 4]};
                mma16(hh[ns], ah, bhf);
                mma16(hl[ns], ah, blf);
                mma16(lh[ns], al, bhf);
            }
        }
        __syncthreads();
    }

    // epilogue: combine, add bias, split to packed bf16x2 hi/lo, store
#pragma unroll
    for (int ns = 0; ns < 4; ns++) {
        const int col = j0 + wc * 32 + ns * 8 + 2 * tg;
        const float b0 = bias[col], b1 = bias[col + 1];
        const int h = col >> 6, cpair = (col & 63) >> 1;
#pragma unroll
        for (int half = 0; half < 2; half++) {
            const int r = r0 + wr * 16 + gid + half * 8;
            const int bb = r >> 10, l = r & 1023;
            const size_t idx = (((size_t)(bb * H_ + h) * N_) + l) * CP_ + cpair;
            const float v0 = hh[ns][half * 2 + 0] + hl[ns][half * 2 + 0] + lh[ns][half * 2 + 0] + b0;
            const float v1 = hh[ns][half * 2 + 1] + hl[ns][half * 2 + 1] + lh[ns][half * 2 + 1] + b1;
            uint32_t hp, lp;
            split2(v0, v1, hp, lp);
            outh[idx] = hp;
            outl[idx] = lp;
        }
    }
}

// ============================================================================
// Kernel 2: FUSED sp + scores + gather/factor/mask + softmax + attn + AV.
// 512 threads, split-bf16 m16n8k16 everywhere, double-buffered staging.
// ============================================================================
__global__ __launch_bounds__(512, 1) void fused_kernel(
    const float* __restrict__ factor, const int* __restrict__ eidx,
    const unsigned char* __restrict__ kmask,
    float* __restrict__ attn, float* __restrict__ hidden)
{
    extern __shared__ float smf[];
    float*    S   = smf;                       // 32 x 1036 fp32 logits
    uint32_t* Su  = (uint32_t*)smf;            // packed probs alias (in-row)
    uint32_t* KH0 = (uint32_t*)(smf + KH0_OFF);
    uint32_t* KL0 = (uint32_t*)(smf + KL0_OFF);
    uint32_t* KH1 = (uint32_t*)(smf + KH1_OFF);
    uint32_t* KL1 = (uint32_t*)(smf + KL1_OFF);
    uint32_t* VH0 = (uint32_t*)(smf + VH0_OFF);
    uint32_t* VL0 = (uint32_t*)(smf + VL0_OFF);
    uint32_t* VH1 = (uint32_t*)(smf + VH1_OFF);
    uint32_t* VL1 = (uint32_t*)(smf + VL1_OFF);
    float*    Sp  = smf + SP_OFF;

    const int tid  = threadIdx.x;
    const int w    = tid >> 5;
    const int lane = tid & 31;
    const int gid  = lane >> 2;
    const int tg   = lane & 3;
    const int wm   = w & 7;
    const int mt   = w >> 3;
    const int bh = blockIdx.y, b = bh >> 2, h = bh & 3;
    const int n0 = blockIdx.x * 32;
    const int r0 = mt * 16 + gid;

    // K/emb staging indices: 64 rows x 32 pairs; thread -> uint4
    const int kst_r = tid >> 3;          // 0..63
    const int kst_c = (tid & 7) * 4;     // 0..28
    // V repack indices: 32 mp x 64 cols
    const int vmp = tid >> 4;            // 0..31
    const int vcp = (tid & 15) * 2;      // source pair col (0..30)

    const uint32_t* kh_base = g_kh + (size_t)bh * M_ * CP_;
    const uint32_t* kl_base = g_kl + (size_t)bh * M_ * CP_;
    const uint32_t* vh_base = g_vh + (size_t)bh * M_ * CP_;
    const uint32_t* vl_base = g_vl + (size_t)bh * M_ * CP_;

    // ---------- stage Q (32 rows x 32 pairs) through KH0/KL0 ----------
    {
        const uint32_t* qh = g_qh + ((size_t)bh * N_ + n0) * CP_;
        const uint32_t* ql = g_ql + ((size_t)bh * N_ + n0) * CP_;
        uint2 q2h = ((const uint2*)qh)[tid];
        uint2 q2l = ((const uint2*)ql)[tid];
        const int qr = tid >> 4, qc = (tid & 15) * 2;
        *(uint2*)&KH0[qr * KB_STRIDE + qc] = q2h;
        *(uint2*)&KL0[qr * KB_STRIDE + qc] = q2l;
    }
    // prefetch emb chunk 0 (64 rows x 32 pairs of head h)
    uint4 eph, epl;
    eph = *(const uint4*)&g_eh[(size_t)kst_r * (D_ / 2) + h * CP_ + kst_c];
    epl = *(const uint4*)&g_el[(size_t)kst_r * (D_ / 2) + h * CP_ + kst_c];
    __syncthreads();

    // ---------- preload Q hi+lo fragments (4 k16-blocks) ----------
    uint32_t qfh[4][4], qfl[4][4];
#pragma unroll
    for (int kb = 0; kb < 4; kb++) {
        const int c0 = kb * 8 + tg;
        qfh[kb][0] = KH0[r0 * KB_STRIDE + c0];
        qfh[kb][1] = KH0[(r0 + 8) * KB_STRIDE + c0];
        qfh[kb][2] = KH0[r0 * KB_STRIDE + c0 + 4];
        qfh[kb][3] = KH0[(r0 + 8) * KB_STRIDE + c0 + 4];
        qfl[kb][0] = KL0[r0 * KB_STRIDE + c0];
        qfl[kb][1] = KL0[(r0 + 8) * KB_STRIDE + c0];
        qfl[kb][2] = KL0[r0 * KB_STRIDE + c0 + 4];
        qfl[kb][3] = KL0[(r0 + 8) * KB_STRIDE + c0 + 4];
    }
    __syncthreads();

    // ---------- SP: Sp(32x128) = Q · emb_h^T (2 chunks) ----------
#pragma unroll
    for (int pc = 0; pc < 2; pc++) {
        uint32_t* Khb = pc ? KH1 : KH0;
        uint32_t* Klb = pc ? KL1 : KL0;
        *(uint4*)&Khb[kst_r * KB_STRIDE + kst_c] = eph;
        *(uint4*)&Klb[kst_r * KB_STRIDE + kst_c] = epl;
        if (pc == 0) {
            eph = *(const uint4*)&g_eh[(size_t)(64 + kst_r) * (D_ / 2) + h * CP_ + kst_c];
            epl = *(const uint4*)&g_el[(size_t)(64 + kst_r) * (D_ / 2) + h * CP_ + kst_c];
        }
        __syncthreads();

        float hh[4] = {}, hl[4] = {}, lh[4] = {};
#pragma unroll
        for (int kb = 0; kb < 4; kb++) {
            const int br = wm * 8 + gid, bc = kb * 8 + tg;
            uint32_t bhf[2] = {Khb[br * KB_STRIDE + bc], Khb[br * KB_STRIDE + bc + 4]};
            uint32_t blf[2] = {Klb[br * KB_STRIDE + bc], Klb[br * KB_STRIDE + bc + 4]};
            mma16(hh, qfh[kb], bhf);
            mma16(hl, qfh[kb], blf);
            mma16(lh, qfl[kb], bhf);
        }
        const int col = pc * 64 + wm * 8 + 2 * tg;
        *(float2*)(Sp + r0 * SP_STRIDE + col) =
            make_float2(hh[0] + hl[0] + lh[0], hh[1] + hl[1] + lh[1]);
        *(float2*)(Sp + (r0 + 8) * SP_STRIDE + col) =
            make_float2(hh[2] + hl[2] + lh[2], hh[3] + hl[3] + lh[3]);
    }
    // prefetch K chunk 0 (linear: (kst_r)*32 + kst_c == tid*4)
    uint4 kph = *(const uint4*)&kh_base[(size_t)tid * 4];
    uint4 kpl = *(const uint4*)&kl_base[(size_t)tid * 4];

    // ---------- GEMM1: S(32x1024) = Q · K^T (16 chunks, 1 sync each) ----------
    for (int mc = 0; mc < 16; mc++) {
        uint32_t* Khb = (mc & 1) ? KH1 : KH0;
        uint32_t* Klb = (mc & 1) ? KL1 : KL0;
        *(uint4*)&Khb[kst_r * KB_STRIDE + kst_c] = kph;
        *(uint4*)&Klb[kst_r * KB_STRIDE + kst_c] = kpl;
        if (mc < 15) {
            const size_t off = (size_t)(mc + 1) * 2048;
            kph = *(const uint4*)&kh_base[off + (size_t)tid * 4];
            kpl = *(const uint4*)&kl_base[off + (size_t)tid * 4];
        }
        __syncthreads();

        float hh[4] = {}, hl[4] = {}, lh[4] = {};
#pragma unroll
        for (int kb = 0; kb < 4; kb++) {
            const int br = wm * 8 + gid, bc = kb * 8 + tg;
            uint32_t bhf[2] = {Khb[br * KB_STRIDE + bc], Khb[br * KB_STRIDE + bc + 4]};
            uint32_t blf[2] = {Klb[br * KB_STRIDE + bc], Klb[br * KB_STRIDE + bc + 4]};
            mma16(hh, qfh[kb], bhf);
            mma16(hl, qfh[kb], blf);
            mma16(lh, qfl[kb], bhf);
        }
        const int col = mc * 64 + wm * 8 + 2 * tg;
        *(float2*)(S + r0 * S_STRIDE + col) =
            make_float2(hh[0] + hl[0] + lh[0], hh[1] + hl[1] + lh[1]);
        *(float2*)(S + (r0 + 8) * S_STRIDE + col) =
            make_float2(hh[2] + hl[2] + lh[2], hh[3] + hl[3] + lh[3]);
    }
    __syncthreads();

    // prefetch V chunk 0 raw pairs (repacked at STS time)
    uint2 pvh0 = *(const uint2*)&vh_base[(size_t)vmp * 64 + vcp];
    uint2 pvh1 = *(const uint2*)&vh_base[(size_t)vmp * 64 + 32 + vcp];
    uint2 pvl0 = *(const uint2*)&vl_base[(size_t)vmp * 64 + vcp];
    uint2 pvl1 = *(const uint2*)&vl_base[(size_t)vmp * 64 + 32 + vcp];

    // ---------- epilogue: gather sp, factor, scale, mask ----------
    {
        const int half = tid >> 8, t2 = tid & 255;
        const int c4 = t2 * 4;
#pragma unroll 4
        for (int it = 0; it < 16; it++) {
            const int row = it * 2 + half;
            const size_t gbase = ((size_t)(b * N_ + n0 + row)) * M_ + c4;
            float4 sc = *(float4*)(S + row * S_STRIDE + c4);
            int4   id = *(const int4*)(eidx + gbase);
            float4 fa = *(const float4*)(factor + gbase);
            const float* sprow = Sp + row * SP_STRIDE;
            float e0 = fa.x * (sc.x + sprow[id.x]) * 0.125f;
            float e1 = fa.y * (sc.y + sprow[id.y]) * 0.125f;
            float e2 = fa.z * (sc.z + sprow[id.z]) * 0.125f;
            float e3 = fa.w * (sc.w + sprow[id.w]) * 0.125f;
            const unsigned char* km = kmask + b * M_ + c4;
            if (km[0]) e0 = -INFINITY;
            if (km[1]) e1 = -INFINITY;
            if (km[2]) e2 = -INFINITY;
            if (km[3]) e3 = -INFINITY;
            *(float4*)(S + row * S_STRIDE + c4) = make_float4(e0, e1, e2, e3);
        }
    }
    __syncthreads();

    // ---------- softmax: warp w owns rows 2w, 2w+1 ----------
    // writes fp32 probs to gmem, packed bf16x2 hi/lo probs in-place into S row
#pragma unroll
    for (int rr = 0; rr < 2; rr++) {
        const int row = w * 2 + rr;
        float vals[32];
        float mx = -INFINITY;
#pragma unroll
        for (int j = 0; j < 8; j++) {
            float4 v = *(float4*)(S + row * S_STRIDE + (j * 32 + lane) * 4);
            vals[j * 4 + 0] = v.x; vals[j * 4 + 1] = v.y;
            vals[j * 4 + 2] = v.z; vals[j * 4 + 3] = v.w;
            mx = fmaxf(mx, fmaxf(fmaxf(v.x, v.y), fmaxf(v.z, v.w)));
        }
#pragma unroll
        for (int off = 16; off > 0; off >>= 1)
            mx = fmaxf(mx, __shfl_xor_sync(0xffffffffu, mx, off));
        float sum = 0.f;
#pragma unroll
        for (int i = 0; i < 32; i++) { vals[i] = __expf(vals[i] - mx); sum += vals[i]; }
#pragma unroll
        for (int off = 16; off > 0; off >>= 1)
            sum += __shfl_xor_sync(0xffffffffu, sum, off);
        const float inv = 1.0f / sum;
        const size_t abase = ((size_t)(bh * N_ + n0 + row)) * M_;
#pragma unroll
        for (int j = 0; j < 8; j++) {
            const int c4 = (j * 32 + lane) * 4;
            const float p0 = vals[j * 4 + 0] * inv, p1 = vals[j * 4 + 1] * inv;
            const float p2 = vals[j * 4 + 2] * inv, p3 = vals[j * 4 + 3] * inv;
            *(float4*)(attn + abase + c4) = make_float4(p0, p1, p2, p3);
            uint32_t hp0, lp0, hp1, lp1;
            split2(p0, p1, hp0, lp0);
            split2(p2, p3, hp1, lp1);
            const int c2 = c4 >> 1;
            *(uint2*)(Su + row * S_STRIDE + c2)       = make_uint2(hp0, hp1);
            *(uint2*)(Su + row * S_STRIDE + 518 + c2) = make_uint2(lp0, lp1);
        }
    }

    // ---------- AV: hidden(32x64) = P · V (16 chunks, repack V to pair-along-M) ----------
    float avhh[4] = {}, avhl[4] = {}, avlh[4] = {};
    for (int kc = 0; kc < 16; kc++) {
        uint32_t* VHb = (kc & 1) ? VH1 : VH0;
        uint32_t* VLb = (kc & 1) ? VL1 : VL0;
        {   // repack + STS: pair-along-M via PRMT 2x2 bf16 transpose
            uint4 oh, ol;
            oh.x = prmtb(pvh0.x, pvh1.x, 0x5410); oh.y = prmtb(pvh0.x, pvh1.x, 0x7632);
            oh.z = prmtb(pvh0.y, pvh1.y, 0x5410); oh.w = prmtb(pvh0.y, pvh1.y, 0x7632);
            ol.x = prmtb(pvl0.x, pvl1.x, 0x5410); ol.y = prmtb(pvl0.x, pvl1.x, 0x7632);
            ol.z = prmtb(pvl0.y, pvl1.y, 0x5410); ol.w = prmtb(pvl0.y, pvl1.y, 0x7632);
            *(uint4*)&VHb[vmp * VB_STRIDE + (tid & 15) * 4] = oh;
            *(uint4*)&VLb[vmp * VB_STRIDE + (tid & 15) * 4] = ol;
        }
        if (kc < 15) {
            const size_t off = (size_t)(kc + 1) * 2048;
            pvh0 = *(const uint2*)&vh_base[off + (size_t)vmp * 64 + vcp];
            pvh1 = *(const uint2*)&vh_base[off + (size_t)vmp * 64 + 32 + vcp];
            pvl0 = *(const uint2*)&vl_base[off + (size_t)vmp * 64 + vcp];
            pvl1 = *(const uint2*)&vl_base[off + (size_t)vmp * 64 + 32 + vcp];
        }
        __syncthreads();

#pragma unroll
        for (int kb = 0; kb < 4; kb++) {
            const int cb = kc * 32 + kb * 8;
            uint32_t ah[4], al[4];
            ah[0] = Su[r0 * S_STRIDE + cb + tg];
            ah[1] = Su[(r0 + 8) * S_STRIDE + cb + tg];
            ah[2] = Su[r0 * S_STRIDE + cb + tg + 4];
            ah[3] = Su[(r0 + 8) * S_STRIDE + cb + tg + 4];
            al[0] = Su[r0 * S_STRIDE + 518 + cb + tg];
            al[1] = Su[(r0 + 8) * S_STRIDE + 518 + cb + tg];
            al[2] = Su[r0 * S_STRIDE + 518 + cb + tg + 4];
            al[3] = Su[(r0 + 8) * S_STRIDE + 518 + cb + tg + 4];
            uint32_t bhf[2], blf[2];
            bhf[0] = VHb[(kb * 8 + tg) * VB_STRIDE + wm * 8 + gid];
            bhf[1] = VHb[(kb * 8 + tg + 4) * VB_STRIDE + wm * 8 + gid];
            blf[0] = VLb[(kb * 8 + tg) * VB_STRIDE + wm * 8 + gid];
            blf[1] = VLb[(kb * 8 + tg + 4) * VB_STRIDE + wm * 8 + gid];
            mma16(avhh, ah, bhf);
            mma16(avhl, ah, blf);
            mma16(avlh, al, bhf);
        }
    }

    // store hidden
    {
        const int row = n0 + r0;
        const int col = h * 64 + wm * 8 + 2 * tg;
        *(float2*)(hidden + ((size_t)b * N_ + row) * D_ + col) =
            make_float2(avhh[0] + avhl[0] + avlh[0], avhh[1] + avhl[1] + avlh[1]);
        *(float2*)(hidden + ((size_t)b * N_ + row + 8) * D_ + col) =
            make_float2(avhh[2] + avhl[2] + avlh[2], avhh[3] + avhl[3] + avlh[3]);
    }
}

// ============================================================================
// Launch
// ============================================================================
extern "C" void kernel_launch(void* const* d_in, const int* in_sizes, int n_in,
                              void* d_out, int out_size)
{
    const float* input_q = (const float*)d_in[0];
    const float* input_k = (const float*)d_in[1];
    const float* input_v = (const float*)d_in[2];
    const float* Wq = (const float*)d_in[3];
    const float* bq = (const float*)d_in[4];
    const float* Wk = (const float*)d_in[5];
    const float* bk = (const float*)d_in[6];
    const float* Wv = (const float*)d_in[7];
    const float* bv = (const float*)d_in[8];
    const float* emb_table = (const float*)d_in[9];
    const float* factor = (const float*)d_in[10];
    const int* eidx = (const int*)d_in[11];
    const unsigned char* kmask = (const unsigned char*)d_in[12];

    float* hidden = (float*)d_out;                          // (B,N,D)
    float* attn   = (float*)d_out + (size_t)B_ * N_ * D_;   // (B,H,N,M)

    static int smem_set = 0;
    if (!smem_set) {
        cudaFuncSetAttribute(fused_kernel,
                             cudaFuncAttributeMaxDynamicSharedMemorySize, SMEM_BYTES);
        smem_set = 1;
    }

    split_kernel<<<(P_ * D_ / 2 + 3 * D_ * D_ / 2) / 256, 256>>>(emb_table, Wq, Wk, Wv);

    proj_kernel<<<dim3((B_ * N_) / 64, D_ / 64, 3), 256>>>(
        input_q, input_k, input_v, bq, bk, bv);

    fused_kernel<<<dim3(N_ / 32, B_ * H_), 512, SMEM_BYTES>>>(
        factor, eidx, kmask, attn, hidden);
}